// round 1
// baseline (speedup 1.0000x reference)
#include <cuda_runtime.h>
#include <cstdint>
#include <cstddef>

#define B_ 8
#define C_ 512
#define S_ 1024
#define NH 8
#define HD 64
#define M_ (B_ * S_)   // 8192

// ---------------- scratch (device globals, no allocation) ----------------
__device__ float g_xs[M_ * C_];
__device__ float g_res[M_ * C_];
__device__ float g_q[M_ * C_];
__device__ float g_k[M_ * C_];
__device__ float g_v[M_ * C_];
__device__ float g_o[M_ * C_];
__device__ float g_out1[M_ * C_];
__device__ float g_h[M_ * C_];
__device__ float g_h1[M_ * C_];
__device__ float g_wq[C_ * C_];
__device__ float g_wk[C_ * C_];
__device__ float g_wv[C_ * C_];

// ---------------- helpers ----------------
__device__ __forceinline__ float blockReduceSum(float v, float* red) {
    #pragma unroll
    for (int o = 16; o; o >>= 1) v += __shfl_xor_sync(0xffffffffu, v, o);
    int wid = threadIdx.x >> 5;
    if ((threadIdx.x & 31) == 0) red[wid] = v;
    __syncthreads();
    float r = (threadIdx.x < 8) ? red[threadIdx.x] : 0.f;
    if (threadIdx.x < 32) {
        #pragma unroll
        for (int o = 4; o; o >>= 1) r += __shfl_xor_sync(0xffffffffu, r, o);
        if (threadIdx.x == 0) red[0] = r;
    }
    __syncthreads();
    float out = red[0];
    __syncthreads();
    return out;
}

// pack Q_W/K_W/V_W (n,c,d) -> (c, n*64+d) row-major
__global__ void pack_qkv_kernel(const float* __restrict__ QW, const float* __restrict__ KW,
                                const float* __restrict__ VW,
                                float* __restrict__ wq, float* __restrict__ wk, float* __restrict__ wv) {
    int idx = blockIdx.x * blockDim.x + threadIdx.x;   // 0 .. 262143
    int c = idx >> 9;
    int j = idx & 511;
    int n = j >> 6, d = j & 63;
    int src = (n * C_ + c) * HD + d;
    wq[idx] = QW[src];
    wk[idx] = KW[src];
    wv[idx] = VW[src];
}

// LN1: reads x (B,C,H,W), emits xs (row-major B*S x C) and res = LN(xs)
__global__ void ln1_kernel(const float* __restrict__ x, const float* __restrict__ g,
                           const float* __restrict__ bt, float* __restrict__ xs,
                           float* __restrict__ res) {
    int row = blockIdx.x;                 // b*1024 + s
    int b = row >> 10, s = row & 1023;
    const float* xp = x + (size_t)b * C_ * S_ + s;
    int tid = threadIdx.x;                // 256
    __shared__ float red[8];
    float v1 = xp[(size_t)tid * S_];
    float v2 = xp[(size_t)(tid + 256) * S_];
    float sum = blockReduceSum(v1 + v2, red);
    float mu = sum * (1.f / 512.f);
    float d1 = v1 - mu, d2 = v2 - mu;
    float var = blockReduceSum(d1 * d1 + d2 * d2, red) * (1.f / 512.f);
    float rstd = rsqrtf(var + 1e-5f);
    size_t ro = (size_t)row * C_;
    xs[ro + tid] = v1;
    xs[ro + tid + 256] = v2;
    res[ro + tid] = d1 * rstd * g[tid] + bt[tid];
    res[ro + tid + 256] = d2 * rstd * g[tid + 256] + bt[tid + 256];
}

// LN2: row-major input -> row-major output
__global__ void ln2_kernel(const float* __restrict__ in, const float* __restrict__ g,
                           const float* __restrict__ bt, float* __restrict__ res) {
    int row = blockIdx.x;
    int tid = threadIdx.x;
    __shared__ float red[8];
    const float* xp = in + (size_t)row * C_;
    float v1 = xp[tid];
    float v2 = xp[tid + 256];
    float sum = blockReduceSum(v1 + v2, red);
    float mu = sum * (1.f / 512.f);
    float d1 = v1 - mu, d2 = v2 - mu;
    float var = blockReduceSum(d1 * d1 + d2 * d2, red) * (1.f / 512.f);
    float rstd = rsqrtf(var + 1e-5f);
    size_t ro = (size_t)row * C_;
    res[ro + tid] = d1 * rstd * g[tid] + bt[tid];
    res[ro + tid + 256] = d2 * rstd * g[tid + 256] + bt[tid + 256];
}

// ---------------- GEMM: C = A(MxK) * B(KxN) + bias [+resid] [gelu] ----------------
// ACT: 0=none 1=gelu(exact).  TRANS_OUT: 0=row-major, 1=write BCHW transposed.
template <int ACT, int TRANS_OUT>
__global__ void gemm_kernel(const float* __restrict__ A, const float* __restrict__ Bm,
                            const float* __restrict__ bias, const float* __restrict__ resid,
                            float* __restrict__ C, int M, int N, int K) {
    __shared__ float As[16][68];   // k-major: As[k][m]
    __shared__ float Bs[16][68];   // Bs[k][n]
    int tid = threadIdx.x;         // 256
    int tx = tid & 15, ty = tid >> 4;
    int row0 = blockIdx.y * 64;
    int col0 = blockIdx.x * 64;
    float acc[4][4] = {};
    for (int k0 = 0; k0 < K; k0 += 16) {
        {   // A tile 64x16 -> transposed
            int r = tid >> 2;
            int kc = (tid & 3) * 4;
            const float4 av = *(const float4*)(A + (size_t)(row0 + r) * K + k0 + kc);
            As[kc + 0][r] = av.x; As[kc + 1][r] = av.y;
            As[kc + 2][r] = av.z; As[kc + 3][r] = av.w;
        }
        {   // B tile 16x64
            int kr = tid >> 4;
            int nc = (tid & 15) * 4;
            *(float4*)&Bs[kr][nc] = *(const float4*)(Bm + (size_t)(k0 + kr) * N + col0 + nc);
        }
        __syncthreads();
        #pragma unroll
        for (int kk = 0; kk < 16; kk++) {
            float a[4], bb[4];
            #pragma unroll
            for (int i = 0; i < 4; i++) a[i] = As[kk][ty * 4 + i];
            #pragma unroll
            for (int j = 0; j < 4; j++) bb[j] = Bs[kk][tx * 4 + j];
            #pragma unroll
            for (int i = 0; i < 4; i++)
                #pragma unroll
                for (int j = 0; j < 4; j++) acc[i][j] += a[i] * bb[j];
        }
        __syncthreads();
    }
    #pragma unroll
    for (int i = 0; i < 4; i++) {
        int r = row0 + ty * 4 + i;
        #pragma unroll
        for (int j = 0; j < 4; j++) {
            int c = col0 + tx * 4 + j;
            float v = acc[i][j] + bias[c];
            if (ACT == 1) v = 0.5f * v * (1.f + erff(v * 0.7071067811865476f));
            if (resid) v += resid[(size_t)r * N + c];
            if (TRANS_OUT) {
                int b = r >> 10, s = r & 1023;
                C[((size_t)b * N + c) * S_ + s] = v;
            } else {
                C[(size_t)r * N + c] = v;
            }
        }
    }
}

// ---------------- fused flash attention (64q x 64k tiles, d=64) ----------------
__global__ void attn_kernel(const float* __restrict__ q, const float* __restrict__ k,
                            const float* __restrict__ v, float* __restrict__ o) {
    extern __shared__ float sm[];
    float (*Qs)[65] = (float(*)[65])sm;
    float (*Ks)[65] = (float(*)[65])(sm + 64 * 65);
    float (*Vs)[65] = (float(*)[65])(sm + 2 * 64 * 65);
    float (*Ss)[65] = (float(*)[65])(sm + 3 * 64 * 65);
    float* mrow = sm + 4 * 64 * 65;
    float* lrow = mrow + 64;
    float* arow = lrow + 64;

    int tid = threadIdx.x;           // 256
    int tx = tid & 15, ty = tid >> 4;
    int qt = blockIdx.x, n = blockIdx.y, b = blockIdx.z;
    size_t qbase = ((size_t)(b * S_ + qt * 64)) * C_ + n * HD;

    // load Q tile (64 x 64)
    #pragma unroll
    for (int it = 0; it < 4; it++) {
        int f = tid + 256 * it;
        int r = f >> 4;
        int dc = (f & 15) * 4;
        float4 qv = *(const float4*)(q + qbase + (size_t)r * C_ + dc);
        Qs[r][dc + 0] = qv.x; Qs[r][dc + 1] = qv.y;
        Qs[r][dc + 2] = qv.z; Qs[r][dc + 3] = qv.w;
    }
    if (tid < 64) { mrow[tid] = -1e30f; lrow[tid] = 0.f; }
    float acc[4][4] = {};
    const float scale = 0.04419417382415922f;   // 1/sqrt(512)

    for (int kt = 0; kt < 16; kt++) {
        __syncthreads();   // protect Ks/Vs/Ss consumers of previous iter + Q/m/l init
        size_t kbase = ((size_t)(b * S_ + kt * 64)) * C_ + n * HD;
        #pragma unroll
        for (int it = 0; it < 4; it++) {
            int f = tid + 256 * it;
            int r = f >> 4;
            int dc = (f & 15) * 4;
            float4 kv = *(const float4*)(k + kbase + (size_t)r * C_ + dc);
            Ks[r][dc + 0] = kv.x; Ks[r][dc + 1] = kv.y;
            Ks[r][dc + 2] = kv.z; Ks[r][dc + 3] = kv.w;
            float4 vv = *(const float4*)(v + kbase + (size_t)r * C_ + dc);
            Vs[r][dc + 0] = vv.x; Vs[r][dc + 1] = vv.y;
            Vs[r][dc + 2] = vv.z; Vs[r][dc + 3] = vv.w;
        }
        __syncthreads();
        // scores S = Q K^T * scale
        float sacc[4][4] = {};
        #pragma unroll 8
        for (int kk = 0; kk < 64; kk++) {
            float a[4], bb[4];
            #pragma unroll
            for (int i = 0; i < 4; i++) a[i] = Qs[ty * 4 + i][kk];
            #pragma unroll
            for (int j = 0; j < 4; j++) bb[j] = Ks[tx * 4 + j][kk];
            #pragma unroll
            for (int i = 0; i < 4; i++)
                #pragma unroll
                for (int j = 0; j < 4; j++) sacc[i][j] += a[i] * bb[j];
        }
        #pragma unroll
        for (int i = 0; i < 4; i++)
            #pragma unroll
            for (int j = 0; j < 4; j++) Ss[ty * 4 + i][tx * 4 + j] = sacc[i][j] * scale;
        __syncthreads();
        // online softmax per row
        if (tid < 64) {
            int r = tid;
            float mx = mrow[r];
            #pragma unroll 8
            for (int j2 = 0; j2 < 64; j2++) mx = fmaxf(mx, Ss[r][j2]);
            float al = __expf(mrow[r] - mx);
            float sum = 0.f;
            #pragma unroll 8
            for (int j2 = 0; j2 < 64; j2++) {
                float p = __expf(Ss[r][j2] - mx);
                Ss[r][j2] = p;
                sum += p;
            }
            lrow[r] = lrow[r] * al + sum;
            mrow[r] = mx;
            arow[r] = al;
        }
        __syncthreads();
        // rescale accumulators and add P @ V
        float al[4];
        #pragma unroll
        for (int i = 0; i < 4; i++) al[i] = arow[ty * 4 + i];
        #pragma unroll
        for (int i = 0; i < 4; i++)
            #pragma unroll
            for (int j = 0; j < 4; j++) acc[i][j] *= al[i];
        #pragma unroll 8
        for (int kk = 0; kk < 64; kk++) {
            float p[4], vv[4];
            #pragma unroll
            for (int i = 0; i < 4; i++) p[i] = Ss[ty * 4 + i][kk];
            #pragma unroll
            for (int j = 0; j < 4; j++) vv[j] = Vs[kk][tx * 4 + j];
            #pragma unroll
            for (int i = 0; i < 4; i++)
                #pragma unroll
                for (int j = 0; j < 4; j++) acc[i][j] += p[i] * vv[j];
        }
    }
    float linv[4];
    #pragma unroll
    for (int i = 0; i < 4; i++) linv[i] = 1.f / lrow[ty * 4 + i];
    #pragma unroll
    for (int i = 0; i < 4; i++)
        #pragma unroll
        for (int j = 0; j < 4; j++)
            o[qbase + (size_t)(ty * 4 + i) * C_ + tx * 4 + j] = acc[i][j] * linv[i];
}

// ---------------- launch ----------------
static constexpr int ATT_SMEM = (4 * 64 * 65 + 3 * 64) * 4;

extern "C" void kernel_launch(void* const* d_in, const int* in_sizes, int n_in,
                              void* d_out, int out_size) {
    (void)in_sizes; (void)n_in; (void)out_size;
    const float* x    = (const float*)d_in[0];
    const float* K_W  = (const float*)d_in[2];
    const float* K_b  = (const float*)d_in[3];
    const float* Q_W  = (const float*)d_in[4];
    const float* Q_b  = (const float*)d_in[5];
    const float* V_W  = (const float*)d_in[6];
    const float* V_b  = (const float*)d_in[7];
    const float* O_W  = (const float*)d_in[8];
    const float* O_b  = (const float*)d_in[9];
    const float* ln1g = (const float*)d_in[10];
    const float* ln1b = (const float*)d_in[11];
    const float* ln2g = (const float*)d_in[12];
    const float* ln2b = (const float*)d_in[13];
    const float* W1   = (const float*)d_in[14];
    const float* b1   = (const float*)d_in[15];
    const float* W2   = (const float*)d_in[16];
    const float* b2   = (const float*)d_in[17];
    float* out = (float*)d_out;

    float *p_xs, *p_res, *p_q, *p_k, *p_v, *p_o, *p_out1, *p_h, *p_h1, *p_wq, *p_wk, *p_wv;
    cudaGetSymbolAddress((void**)&p_xs, g_xs);
    cudaGetSymbolAddress((void**)&p_res, g_res);
    cudaGetSymbolAddress((void**)&p_q, g_q);
    cudaGetSymbolAddress((void**)&p_k, g_k);
    cudaGetSymbolAddress((void**)&p_v, g_v);
    cudaGetSymbolAddress((void**)&p_o, g_o);
    cudaGetSymbolAddress((void**)&p_out1, g_out1);
    cudaGetSymbolAddress((void**)&p_h, g_h);
    cudaGetSymbolAddress((void**)&p_h1, g_h1);
    cudaGetSymbolAddress((void**)&p_wq, g_wq);
    cudaGetSymbolAddress((void**)&p_wk, g_wk);
    cudaGetSymbolAddress((void**)&p_wv, g_wv);

    cudaFuncSetAttribute(attn_kernel, cudaFuncAttributeMaxDynamicSharedMemorySize, ATT_SMEM);

    // 1. pack QKV weights
    pack_qkv_kernel<<<(C_ * C_) / 256, 256>>>(Q_W, K_W, V_W, p_wq, p_wk, p_wv);
    // 2. LN1 + transpose to (B*S, C)
    ln1_kernel<<<M_, 256>>>(x, ln1g, ln1b, p_xs, p_res);
    // 3. Q,K,V projections
    dim3 ggrid(C_ / 64, M_ / 64);
    gemm_kernel<0, 0><<<ggrid, 256>>>(p_res, p_wq, Q_b, nullptr, p_q, M_, C_, C_);
    gemm_kernel<0, 0><<<ggrid, 256>>>(p_res, p_wk, K_b, nullptr, p_k, M_, C_, C_);
    gemm_kernel<0, 0><<<ggrid, 256>>>(p_res, p_wv, V_b, nullptr, p_v, M_, C_, C_);
    // 4. attention
    dim3 agrid(S_ / 64, NH, B_);
    attn_kernel<<<agrid, 256, ATT_SMEM>>>(p_q, p_k, p_v, p_o);
    // 5. output projection + residual (O_W is already (n*64+d, c) row-major)
    gemm_kernel<0, 0><<<ggrid, 256>>>(p_o, O_W, O_b, p_xs, p_out1, M_, C_, C_);
    // 6. LN2
    ln2_kernel<<<M_, 256>>>(p_out1, ln2g, ln2b, p_h);
    // 7. MLP fc1 + exact GELU
    gemm_kernel<1, 0><<<ggrid, 256>>>(p_h, W1, b1, nullptr, p_h1, M_, C_, C_);
    // 8. MLP fc2 + residual, transposed store to (B,C,H,W)
    gemm_kernel<0, 1><<<ggrid, 256>>>(p_h1, W2, b2, p_out1, out, M_, C_, C_);
}

// round 3
// speedup vs baseline: 1.8437x; 1.8437x over previous
#include <cuda_runtime.h>
#include <cuda_bf16.h>
#include <cstdint>
#include <cstddef>

#define B_ 8
#define C_ 512
#define S_ 1024
#define NH 8
#define HD 64
#define M_ (B_ * S_)   // 8192
#define NQKV 1536

#if defined(__CUDA_ARCH__) && (__CUDA_ARCH__ >= 1000) && defined(__CUDA_ARCH_FEAT_SM103_ALL)
#define HAS_TCGEN05 1
#else
#define HAS_TCGEN05 0
#endif

// ---------------- scratch (device globals, no allocation) ----------------
__device__ float g_xs[M_ * C_];
__device__ float g_res[M_ * C_];
__device__ float g_qkv[M_ * NQKV];
__device__ float g_o[M_ * C_];
__device__ float g_out1[M_ * C_];
__device__ float g_h[M_ * C_];
__device__ float g_h1[M_ * C_];
__device__ __nv_bfloat16 g_wqkv_h[NQKV * C_];
__device__ __nv_bfloat16 g_wqkv_l[NQKV * C_];
__device__ __nv_bfloat16 g_wo_h[C_ * C_];
__device__ __nv_bfloat16 g_wo_l[C_ * C_];
__device__ __nv_bfloat16 g_w1_h[C_ * C_];
__device__ __nv_bfloat16 g_w1_l[C_ * C_];
__device__ __nv_bfloat16 g_w2_h[C_ * C_];
__device__ __nv_bfloat16 g_w2_l[C_ * C_];
__device__ float g_bqkv[NQKV];

// ---------------- PTX helpers ----------------
__device__ __forceinline__ uint32_t smem_to_u32(const void* p) {
    uint32_t a;
    asm("{ .reg .u64 t; cvta.to.shared.u64 t, %1; cvt.u32.u64 %0, t; }" : "=r"(a) : "l"(p));
    return a;
}
__device__ __forceinline__ uint32_t sw128(uint32_t off) { return off ^ ((off >> 3) & 0x70); }

#if HAS_TCGEN05
__device__ __forceinline__ uint32_t elect_one_pred() {
    uint32_t pred;
    asm volatile(
        "{\n\t.reg .pred p;\n\telect.sync _|p, 0xFFFFFFFF;\n\tselp.b32 %0, 1, 0, p;\n\t}"
        : "=r"(pred));
    return pred;
}
#define TCGEN05_ALLOC(smem_addr, nCols) \
    asm volatile("tcgen05.alloc.cta_group::1.sync.aligned.shared::cta.b32 [%0], %1;" \
        :: "r"((uint32_t)(smem_addr)), "r"((uint32_t)(nCols)) : "memory")
#define TCGEN05_DEALLOC(tmem_addr, nCols) \
    asm volatile("tcgen05.dealloc.cta_group::1.sync.aligned.b32 %0, %1;" \
        :: "r"(tmem_addr), "r"((uint32_t)(nCols)))
#define TCGEN05_RELINQ() \
    asm volatile("tcgen05.relinquish_alloc_permit.cta_group::1.sync.aligned;")
#define TCGEN05_COMMIT(mbar) \
    asm volatile("tcgen05.commit.cta_group::1.mbarrier::arrive::one.shared::cluster.b64 [%0];" \
        :: "r"((uint32_t)(mbar)) : "memory")
#define TCGEN05_FENCE_AFTER() asm volatile("tcgen05.fence::after_thread_sync;" ::: "memory")
#define TCGEN05_WAIT_LD() asm volatile("tcgen05.wait::ld.sync.aligned;" ::: "memory")
#define FENCE_ASYNC_SHARED() asm volatile("fence.proxy.async.shared::cta;" ::: "memory")
#define MBARRIER_INIT(mbar, cnt) \
    asm volatile("mbarrier.init.shared.b64 [%0], %1;" :: "r"((uint32_t)(mbar)), "r"((uint32_t)(cnt)) : "memory")
#define MBARRIER_INVAL(mbar) \
    asm volatile("mbarrier.inval.shared.b64 [%0];" :: "r"((uint32_t)(mbar)) : "memory")
#define MBARRIER_WAIT_PARITY(mbar, phase) do { \
    uint32_t _m = (uint32_t)(mbar); uint32_t _p = (uint32_t)(phase); uint32_t _d; \
    asm volatile("{\n\t.reg .pred p;\n\t" \
        "mbarrier.try_wait.parity.acquire.cta.shared::cta.b64 p, [%1], %2;\n\t" \
        "selp.b32 %0, 1, 0, p;\n\t}" : "=r"(_d) : "r"(_m), "r"(_p) : "memory"); \
    if (!_d) { \
        asm volatile("{\n\t.reg .pred P1;\n\t" \
            "WL_%=:\n\t" \
            "mbarrier.try_wait.parity.acquire.cta.shared::cta.b64 P1, [%0], %1, 0x989680;\n\t" \
            "@P1 bra.uni WD_%=;\n\t" \
            "bra.uni WL_%=;\n\t" \
            "WD_%=:\n\t}" :: "r"(_m), "r"(_p) : "memory"); \
    } \
} while (0)
#define TCGEN05_LD_X32(r, addr) \
    asm volatile("tcgen05.ld.sync.aligned.32x32b.x32.b32 " \
        "{%0, %1, %2, %3, %4, %5, %6, %7, %8, %9, %10, %11, %12, %13, %14, %15, " \
        " %16, %17, %18, %19, %20, %21, %22, %23, %24, %25, %26, %27, %28, %29, %30, %31}, [%32];" \
        : "=r"((r)[0]), "=r"((r)[1]), "=r"((r)[2]), "=r"((r)[3]), \
          "=r"((r)[4]), "=r"((r)[5]), "=r"((r)[6]), "=r"((r)[7]), \
          "=r"((r)[8]), "=r"((r)[9]), "=r"((r)[10]), "=r"((r)[11]), \
          "=r"((r)[12]), "=r"((r)[13]), "=r"((r)[14]), "=r"((r)[15]), \
          "=r"((r)[16]), "=r"((r)[17]), "=r"((r)[18]), "=r"((r)[19]), \
          "=r"((r)[20]), "=r"((r)[21]), "=r"((r)[22]), "=r"((r)[23]), \
          "=r"((r)[24]), "=r"((r)[25]), "=r"((r)[26]), "=r"((r)[27]), \
          "=r"((r)[28]), "=r"((r)[29]), "=r"((r)[30]), "=r"((r)[31]) \
        : "r"(addr))

static constexpr uint64_t SMEM_DESC_BASE_SW128 =
    (uint64_t(2) << 61) | (uint64_t(1) << 46) | (uint64_t(64) << 32) | (uint64_t(1) << 16);
__device__ __forceinline__ uint64_t make_desc(uint32_t addr) {
    return SMEM_DESC_BASE_SW128 | ((uint64_t)(addr >> 4) & 0x3FFF);
}
__device__ __forceinline__ void mma_f16_ss(uint32_t d, uint64_t a, uint64_t b,
                                           uint32_t idesc, uint32_t en) {
    asm volatile(
        "{\n\t.reg .pred p;\n\tsetp.ne.u32 p, %4, 0;\n\t"
        "tcgen05.mma.cta_group::1.kind::f16 [%0], %1, %2, %3, {%5, %5, %5, %5}, p;\n\t}"
        :: "r"(d), "l"(a), "l"(b), "r"(idesc), "r"(en), "r"(0u) : "memory");
}
// idesc: F32 accum, BF16 a/b, N=128, M=128
static constexpr uint32_t IDESC = (1u << 4) | (1u << 7) | (1u << 10) | (16u << 17) | (8u << 24);
#endif  // HAS_TCGEN05

// warp-level mma.sync fallback (sm_80+ PTX, works on plain sm_103 target)
__device__ __forceinline__ void mma_bf16(float* c, const uint32_t* a, const uint32_t* b) {
    asm volatile(
        "mma.sync.aligned.m16n8k16.row.col.f32.bf16.bf16.f32 "
        "{%0,%1,%2,%3}, {%4,%5,%6,%7}, {%8,%9}, {%0,%1,%2,%3};"
        : "+f"(c[0]), "+f"(c[1]), "+f"(c[2]), "+f"(c[3])
        : "r"(a[0]), "r"(a[1]), "r"(a[2]), "r"(a[3]), "r"(b[0]), "r"(b[1]));
}
__device__ __forceinline__ uint32_t lds32(uint32_t addr) {
    uint32_t v;
    asm volatile("ld.shared.b32 %0, [%1];" : "=r"(v) : "r"(addr));
    return v;
}

// ---------------- small helpers ----------------
__device__ __forceinline__ float blockReduceSum(float v, float* red) {
    #pragma unroll
    for (int o = 16; o; o >>= 1) v += __shfl_xor_sync(0xffffffffu, v, o);
    int wid = threadIdx.x >> 5;
    if ((threadIdx.x & 31) == 0) red[wid] = v;
    __syncthreads();
    float r = (threadIdx.x < 8) ? red[threadIdx.x] : 0.f;
    if (threadIdx.x < 32) {
        #pragma unroll
        for (int o = 4; o; o >>= 1) r += __shfl_xor_sync(0xffffffffu, r, o);
        if (threadIdx.x == 0) red[0] = r;
    }
    __syncthreads();
    float out = red[0];
    __syncthreads();
    return out;
}

__device__ __forceinline__ void split_bf16(float v, __nv_bfloat16& h, __nv_bfloat16& l) {
    h = __float2bfloat16(v);
    l = __float2bfloat16(v - __bfloat162float(h));
}

// ---------------- pack kernels ----------------
__global__ void pack_qkvw(const float* __restrict__ QW, const float* __restrict__ KW,
                          const float* __restrict__ VW,
                          __nv_bfloat16* __restrict__ wh, __nv_bfloat16* __restrict__ wl) {
    __shared__ float t[32][33];
    int sel = blockIdx.z >> 3, n = blockIdx.z & 7;
    const float* src = sel == 0 ? QW : (sel == 1 ? KW : VW);
    int c0 = blockIdx.x * 32, d0 = blockIdx.y * 32;
    int lx = threadIdx.x & 31, ly = threadIdx.x >> 5;
    #pragma unroll
    for (int i = 0; i < 4; i++)
        t[ly + i * 8][lx] = src[((size_t)n * C_ + c0 + ly + i * 8) * HD + d0 + lx];
    __syncthreads();
    #pragma unroll
    for (int i = 0; i < 4; i++) {
        int row = sel * 512 + n * 64 + d0 + ly + i * 8;
        float v = t[lx][ly + i * 8];
        __nv_bfloat16 h, l; split_bf16(v, h, l);
        wh[(size_t)row * C_ + c0 + lx] = h;
        wl[(size_t)row * C_ + c0 + lx] = l;
    }
}
__global__ void pack_w3(const float* __restrict__ OW, const float* __restrict__ W1,
                        const float* __restrict__ W2,
                        __nv_bfloat16* __restrict__ oh, __nv_bfloat16* __restrict__ ol,
                        __nv_bfloat16* __restrict__ h1, __nv_bfloat16* __restrict__ l1,
                        __nv_bfloat16* __restrict__ h2, __nv_bfloat16* __restrict__ l2) {
    __shared__ float t[32][33];
    const float* src = blockIdx.z == 0 ? OW : (blockIdx.z == 1 ? W1 : W2);
    __nv_bfloat16* dh = blockIdx.z == 0 ? oh : (blockIdx.z == 1 ? h1 : h2);
    __nv_bfloat16* dl = blockIdx.z == 0 ? ol : (blockIdx.z == 1 ? l1 : l2);
    int n0 = blockIdx.x * 32, k0 = blockIdx.y * 32;
    int lx = threadIdx.x & 31, ly = threadIdx.x >> 5;
    #pragma unroll
    for (int i = 0; i < 4; i++)
        t[ly + i * 8][lx] = src[(size_t)(k0 + ly + i * 8) * C_ + n0 + lx];
    __syncthreads();
    #pragma unroll
    for (int i = 0; i < 4; i++) {
        int n = n0 + ly + i * 8;
        float v = t[lx][ly + i * 8];
        __nv_bfloat16 h, l; split_bf16(v, h, l);
        dh[(size_t)n * C_ + k0 + lx] = h;
        dl[(size_t)n * C_ + k0 + lx] = l;
    }
}
__global__ void pack_bias(const float* __restrict__ Qb, const float* __restrict__ Kb,
                          const float* __restrict__ Vb, float* __restrict__ b) {
    int j = blockIdx.x * blockDim.x + threadIdx.x;
    if (j < 512) b[j] = Qb[j];
    else if (j < 1024) b[j] = Kb[j - 512];
    else if (j < 1536) b[j] = Vb[j - 1024];
}

// ---------------- transposes ----------------
__global__ void transpose_in(const float* __restrict__ x, float* __restrict__ xs) {
    __shared__ float t[32][33];
    int c0 = blockIdx.x * 32, r0 = blockIdx.y * 32;
    int b = r0 >> 10, s0 = r0 & 1023;
    int lx = threadIdx.x & 31, ly = threadIdx.x >> 5;
    #pragma unroll
    for (int i = 0; i < 4; i++)
        t[ly + i * 8][lx] = x[((size_t)b * C_ + c0 + ly + i * 8) * S_ + s0 + lx];
    __syncthreads();
    #pragma unroll
    for (int i = 0; i < 4; i++)
        xs[(size_t)(r0 + ly + i * 8) * C_ + c0 + lx] = t[lx][ly + i * 8];
}
__global__ void transpose_out(const float* __restrict__ in, float* __restrict__ out) {
    __shared__ float t[32][33];
    int c0 = blockIdx.x * 32, r0 = blockIdx.y * 32;
    int b = r0 >> 10, s0 = r0 & 1023;
    int lx = threadIdx.x & 31, ly = threadIdx.x >> 5;
    #pragma unroll
    for (int i = 0; i < 4; i++)
        t[ly + i * 8][lx] = in[(size_t)(r0 + ly + i * 8) * C_ + c0 + lx];
    __syncthreads();
    #pragma unroll
    for (int i = 0; i < 4; i++)
        out[((size_t)b * C_ + c0 + ly + i * 8) * S_ + s0 + lx] = t[lx][ly + i * 8];
}

// ---------------- LayerNorm over rows ----------------
__global__ void ln_rows(const float* __restrict__ in, const float* __restrict__ g,
                        const float* __restrict__ bt, float* __restrict__ res) {
    int row = blockIdx.x;
    int tid = threadIdx.x;
    __shared__ float red[8];
    const float* xp = in + (size_t)row * C_;
    float v1 = xp[tid];
    float v2 = xp[tid + 256];
    float sum = blockReduceSum(v1 + v2, red);
    float mu = sum * (1.f / 512.f);
    float d1 = v1 - mu, d2 = v2 - mu;
    float var = blockReduceSum(d1 * d1 + d2 * d2, red) * (1.f / 512.f);
    float rstd = rsqrtf(var + 1e-5f);
    size_t ro = (size_t)row * C_;
    res[ro + tid] = d1 * rstd * g[tid] + bt[tid];
    res[ro + tid + 256] = d2 * rstd * g[tid + 256] + bt[tid + 256];
}

// ---------------- tensor-core GEMM: C = A(Mx512)*B^T + bias [gelu] [+resid] ----------------
// B given as bf16 hi/lo [N][512] K-major. Tile 128x128, K-chunk 64. bf16x3 compensation.
static constexpr int SM_AH = 1024;
static constexpr int SM_AL = SM_AH + 16384;
static constexpr int SM_BH = SM_AL + 16384;
static constexpr int SM_BL = SM_BH + 16384;
static constexpr int GEMM_SMEM = SM_BL + 16384;   // 66560

template <int ACT, int RESID>
__global__ void __launch_bounds__(256, 2)
tc_gemm(const float* __restrict__ A, const __nv_bfloat16* __restrict__ Bh,
        const __nv_bfloat16* __restrict__ Bl, const float* __restrict__ bias,
        const float* __restrict__ resid, float* __restrict__ Cout, int ld_out) {
    extern __shared__ char smem[];
    uint32_t sb = smem_to_u32(smem);
    int tid = threadIdx.x;
    int wid = tid >> 5;
    int lid = tid & 31;
    int col0 = blockIdx.x * 128;
    int row0 = blockIdx.y * 128;

#if HAS_TCGEN05
    if (wid == 0) { TCGEN05_ALLOC(sb, 128); TCGEN05_RELINQ(); }
    if (tid == 0) MBARRIER_INIT(sb + 8, 1);
    __syncthreads();
    uint32_t tmem;
    asm volatile("ld.shared.b32 %0, [%1];" : "=r"(tmem) : "r"(sb));
#else
    float acc[2][8][4] = {};   // [m-frag][n-tile][regs]
    int grp = lid >> 2;
    int qd = lid & 3;
    int wr = wid >> 1;         // 0..3 -> m offset
    int wc = wid & 1;          // 0..1 -> n offset
    int m_base = wr * 32;
    int n_base = wc * 64;
#endif

    for (int c = 0; c < 8; c++) {
#if HAS_TCGEN05
        if (c > 0) MBARRIER_WAIT_PARITY(sb + 8, (c - 1) & 1);
#endif
        int k0 = c * 64;
        // A tile: 128 rows x 64 fp32 -> bf16 hi/lo swizzled
        #pragma unroll
        for (int it = 0; it < 8; it++) {
            int f = tid + 256 * it;
            int r = f >> 4;
            int c4 = (f & 15) * 4;
            float4 av = *(const float4*)(A + (size_t)(row0 + r) * C_ + k0 + c4);
            __nv_bfloat16 hx, lx_, hy, ly_, hz, lz_, hw, lw_;
            split_bf16(av.x, hx, lx_); split_bf16(av.y, hy, ly_);
            split_bf16(av.z, hz, lz_); split_bf16(av.w, hw, lw_);
            uint32_t h01 = ((uint32_t)__bfloat16_as_ushort(hy) << 16) | __bfloat16_as_ushort(hx);
            uint32_t h23 = ((uint32_t)__bfloat16_as_ushort(hw) << 16) | __bfloat16_as_ushort(hz);
            uint32_t l01 = ((uint32_t)__bfloat16_as_ushort(ly_) << 16) | __bfloat16_as_ushort(lx_);
            uint32_t l23 = ((uint32_t)__bfloat16_as_ushort(lw_) << 16) | __bfloat16_as_ushort(lz_);
            uint32_t off = sw128((uint32_t)(r * 128 + c4 * 2));
            *(uint2*)(smem + SM_AH + off) = make_uint2(h01, h23);
            *(uint2*)(smem + SM_AL + off) = make_uint2(l01, l23);
        }
        // B tiles: 128 rows x 64 bf16 (128B rows)
        #pragma unroll
        for (int it = 0; it < 4; it++) {
            int f = tid + 256 * it;
            int r = f >> 3;
            int u = f & 7;
            size_t gi = (size_t)(col0 + r) * C_ + k0 + u * 8;
            uint32_t off = sw128((uint32_t)(r * 128 + u * 16));
            *(uint4*)(smem + SM_BH + off) = *(const uint4*)(Bh + gi);
            *(uint4*)(smem + SM_BL + off) = *(const uint4*)(Bl + gi);
        }
        __syncthreads();
#if HAS_TCGEN05
        if (wid == 0) {
            FENCE_ASYNC_SHARED();
            if (elect_one_pred()) {
                uint64_t dAh = make_desc(sb + SM_AH);
                uint64_t dAl = make_desc(sb + SM_AL);
                uint64_t dBh = make_desc(sb + SM_BH);
                uint64_t dBl = make_desc(sb + SM_BL);
                #pragma unroll
                for (int ks = 0; ks < 4; ks++) {
                    uint32_t en0 = !(c == 0 && ks == 0);
                    mma_f16_ss(tmem, dAh + ks * 2, dBh + ks * 2, IDESC, en0);
                    mma_f16_ss(tmem, dAh + ks * 2, dBl + ks * 2, IDESC, 1u);
                    mma_f16_ss(tmem, dAl + ks * 2, dBh + ks * 2, IDESC, 1u);
                }
                TCGEN05_COMMIT(sb + 8);
            }
        }
#else
        #pragma unroll
        for (int ks = 0; ks < 4; ks++) {
            int kk = ks * 16 + qd * 2;
            uint32_t ah[2][4], al[2][4];
            #pragma unroll
            for (int f2 = 0; f2 < 2; f2++) {
                int m = m_base + f2 * 16 + grp;
                uint32_t o00 = sw128((uint32_t)(m * 128 + kk * 2));
                uint32_t o10 = sw128((uint32_t)((m + 8) * 128 + kk * 2));
                uint32_t o01 = sw128((uint32_t)(m * 128 + (kk + 8) * 2));
                uint32_t o11 = sw128((uint32_t)((m + 8) * 128 + (kk + 8) * 2));
                ah[f2][0] = lds32(sb + SM_AH + o00); ah[f2][1] = lds32(sb + SM_AH + o10);
                ah[f2][2] = lds32(sb + SM_AH + o01); ah[f2][3] = lds32(sb + SM_AH + o11);
                al[f2][0] = lds32(sb + SM_AL + o00); al[f2][1] = lds32(sb + SM_AL + o10);
                al[f2][2] = lds32(sb + SM_AL + o01); al[f2][3] = lds32(sb + SM_AL + o11);
            }
            #pragma unroll
            for (int t = 0; t < 8; t++) {
                int n = n_base + t * 8 + grp;
                uint32_t o0 = sw128((uint32_t)(n * 128 + kk * 2));
                uint32_t o1 = sw128((uint32_t)(n * 128 + (kk + 8) * 2));
                uint32_t bh[2], bl[2];
                bh[0] = lds32(sb + SM_BH + o0); bh[1] = lds32(sb + SM_BH + o1);
                bl[0] = lds32(sb + SM_BL + o0); bl[1] = lds32(sb + SM_BL + o1);
                #pragma unroll
                for (int f2 = 0; f2 < 2; f2++) {
                    mma_bf16(acc[f2][t], ah[f2], bh);
                    mma_bf16(acc[f2][t], ah[f2], bl);
                    mma_bf16(acc[f2][t], al[f2], bh);
                }
            }
        }
        __syncthreads();
#endif
    }

#if HAS_TCGEN05
    MBARRIER_WAIT_PARITY(sb + 8, 1);
    TCGEN05_FENCE_AFTER();
    // epilogue: 4 groups of 32 columns, staged through SMEM for coalesced stores
    float* sbuf = (float*)(smem + 1024);   // [128][36]
    for (int g = 0; g < 4; g++) {
        __syncthreads();
        if (wid < 4) {
            uint32_t r32[32];
            TCGEN05_LD_X32(r32, tmem + g * 32);
            TCGEN05_WAIT_LD();
            int m = wid * 32 + lid;
            #pragma unroll
            for (int j4 = 0; j4 < 8; j4++)
                *(float4*)&sbuf[m * 36 + j4 * 4] =
                    make_float4(__uint_as_float(r32[j4 * 4]), __uint_as_float(r32[j4 * 4 + 1]),
                                __uint_as_float(r32[j4 * 4 + 2]), __uint_as_float(r32[j4 * 4 + 3]));
        }
        __syncthreads();
        #pragma unroll
        for (int it = 0; it < 4; it++) {
            int f = tid + 256 * it;
            int r = f >> 3;
            int c4 = (f & 7) * 4;
            int col = col0 + g * 32 + c4;
            float4 v = *(float4*)&sbuf[r * 36 + c4];
            float vv[4] = {v.x, v.y, v.z, v.w};
            #pragma unroll
            for (int j = 0; j < 4; j++) {
                float t = vv[j] + bias[col + j];
                if (ACT == 1) t = 0.5f * t * (1.f + erff(t * 0.7071067811865476f));
                vv[j] = t;
            }
            if (RESID) {
                float4 rv = *(const float4*)(resid + (size_t)(row0 + r) * C_ + col);
                vv[0] += rv.x; vv[1] += rv.y; vv[2] += rv.z; vv[3] += rv.w;
            }
            *(float4*)(Cout + (size_t)(row0 + r) * ld_out + col) =
                make_float4(vv[0], vv[1], vv[2], vv[3]);
        }
    }
    __syncthreads();
    if (tid == 0) MBARRIER_INVAL(sb + 8);
    __syncthreads();
    if (wid == 0) TCGEN05_DEALLOC(tmem, 128);
#else
    // register-direct epilogue
    #pragma unroll
    for (int f2 = 0; f2 < 2; f2++) {
        #pragma unroll
        for (int rr = 0; rr < 2; rr++) {
            int r = row0 + m_base + f2 * 16 + grp + rr * 8;
            #pragma unroll
            for (int t = 0; t < 8; t++) {
                int col = col0 + n_base + t * 8 + qd * 2;
                float v0 = acc[f2][t][rr * 2 + 0] + bias[col];
                float v1 = acc[f2][t][rr * 2 + 1] + bias[col + 1];
                if (ACT == 1) {
                    v0 = 0.5f * v0 * (1.f + erff(v0 * 0.7071067811865476f));
                    v1 = 0.5f * v1 * (1.f + erff(v1 * 0.7071067811865476f));
                }
                if (RESID) {
                    float2 rv = *(const float2*)(resid + (size_t)r * C_ + col);
                    v0 += rv.x; v1 += rv.y;
                }
                *(float2*)(Cout + (size_t)r * ld_out + col) = make_float2(v0, v1);
            }
        }
    }
#endif
}

// ---------------- fused flash attention (64q x 64k tiles, d=64) ----------------
__global__ void attn_kernel(const float* __restrict__ qkv, float* __restrict__ o) {
    extern __shared__ float sm[];
    float (*Qs)[65] = (float(*)[65])sm;
    float (*Ks)[65] = (float(*)[65])(sm + 64 * 65);
    float (*Vs)[65] = (float(*)[65])(sm + 2 * 64 * 65);
    float (*Ss)[65] = (float(*)[65])(sm + 3 * 64 * 65);
    float* mrow = sm + 4 * 64 * 65;
    float* lrow = mrow + 64;
    float* arow = lrow + 64;

    int tid = threadIdx.x;           // 256
    int tx = tid & 15, ty = tid >> 4;
    int qt = blockIdx.x, n = blockIdx.y, b = blockIdx.z;
    size_t qbase = ((size_t)(b * S_ + qt * 64)) * NQKV + n * HD;
    size_t obase = ((size_t)(b * S_ + qt * 64)) * C_ + n * HD;

    #pragma unroll
    for (int it = 0; it < 4; it++) {
        int f = tid + 256 * it;
        int r = f >> 4;
        int dc = (f & 15) * 4;
        float4 qv = *(const float4*)(qkv + qbase + (size_t)r * NQKV + dc);
        Qs[r][dc + 0] = qv.x; Qs[r][dc + 1] = qv.y;
        Qs[r][dc + 2] = qv.z; Qs[r][dc + 3] = qv.w;
    }
    if (tid < 64) { mrow[tid] = -1e30f; lrow[tid] = 0.f; }
    float acc[4][4] = {};
    const float scale = 0.04419417382415922f;   // 1/sqrt(512)

    for (int kt = 0; kt < 16; kt++) {
        __syncthreads();
        size_t kbase = ((size_t)(b * S_ + kt * 64)) * NQKV + n * HD + 512;
        #pragma unroll
        for (int it = 0; it < 4; it++) {
            int f = tid + 256 * it;
            int r = f >> 4;
            int dc = (f & 15) * 4;
            float4 kv = *(const float4*)(qkv + kbase + (size_t)r * NQKV + dc);
            Ks[r][dc + 0] = kv.x; Ks[r][dc + 1] = kv.y;
            Ks[r][dc + 2] = kv.z; Ks[r][dc + 3] = kv.w;
            float4 vv = *(const float4*)(qkv + kbase + 512 + (size_t)r * NQKV + dc);
            Vs[r][dc + 0] = vv.x; Vs[r][dc + 1] = vv.y;
            Vs[r][dc + 2] = vv.z; Vs[r][dc + 3] = vv.w;
        }
        __syncthreads();
        float sacc[4][4] = {};
        #pragma unroll 8
        for (int kk = 0; kk < 64; kk++) {
            float a[4], bb[4];
            #pragma unroll
            for (int i = 0; i < 4; i++) a[i] = Qs[ty * 4 + i][kk];
            #pragma unroll
            for (int j = 0; j < 4; j++) bb[j] = Ks[tx * 4 + j][kk];
            #pragma unroll
            for (int i = 0; i < 4; i++)
                #pragma unroll
                for (int j = 0; j < 4; j++) sacc[i][j] += a[i] * bb[j];
        }
        #pragma unroll
        for (int i = 0; i < 4; i++)
            #pragma unroll
            for (int j = 0; j < 4; j++) Ss[ty * 4 + i][tx * 4 + j] = sacc[i][j] * scale;
        __syncthreads();
        // online softmax, 4 threads per row
        {
            int r = tid >> 2, qd = tid & 3;
            float mold = mrow[r];
            float mx = mold;
            #pragma unroll
            for (int j2 = 0; j2 < 16; j2++) mx = fmaxf(mx, Ss[r][qd * 16 + j2]);
            mx = fmaxf(mx, __shfl_xor_sync(0xffffffffu, mx, 1));
            mx = fmaxf(mx, __shfl_xor_sync(0xffffffffu, mx, 2));
            float sum = 0.f;
            #pragma unroll
            for (int j2 = 0; j2 < 16; j2++) {
                float p = __expf(Ss[r][qd * 16 + j2] - mx);
                Ss[r][qd * 16 + j2] = p;
                sum += p;
            }
            sum += __shfl_xor_sync(0xffffffffu, sum, 1);
            sum += __shfl_xor_sync(0xffffffffu, sum, 2);
            if (qd == 0) {
                float al = __expf(mold - mx);
                arow[r] = al;
                lrow[r] = lrow[r] * al + sum;
                mrow[r] = mx;
            }
        }
        __syncthreads();
        float al[4];
        #pragma unroll
        for (int i = 0; i < 4; i++) al[i] = arow[ty * 4 + i];
        #pragma unroll
        for (int i = 0; i < 4; i++)
            #pragma unroll
            for (int j = 0; j < 4; j++) acc[i][j] *= al[i];
        #pragma unroll 8
        for (int kk = 0; kk < 64; kk++) {
            float p[4], vv[4];
            #pragma unroll
            for (int i = 0; i < 4; i++) p[i] = Ss[ty * 4 + i][kk];
            #pragma unroll
            for (int j = 0; j < 4; j++) vv[j] = Vs[kk][tx * 4 + j];
            #pragma unroll
            for (int i = 0; i < 4; i++)
                #pragma unroll
                for (int j = 0; j < 4; j++) acc[i][j] += p[i] * vv[j];
        }
    }
    float linv[4];
    #pragma unroll
    for (int i = 0; i < 4; i++) linv[i] = 1.f / lrow[ty * 4 + i];
    #pragma unroll
    for (int i = 0; i < 4; i++)
        #pragma unroll
        for (int j = 0; j < 4; j++)
            o[obase + (size_t)(ty * 4 + i) * C_ + tx * 4 + j] = acc[i][j] * linv[i];
}

// ---------------- launch ----------------
static constexpr int ATT_SMEM = (4 * 64 * 65 + 3 * 64) * 4;

extern "C" void kernel_launch(void* const* d_in, const int* in_sizes, int n_in,
                              void* d_out, int out_size) {
    (void)in_sizes; (void)n_in; (void)out_size;
    const float* x    = (const float*)d_in[0];
    const float* K_W  = (const float*)d_in[2];
    const float* K_b  = (const float*)d_in[3];
    const float* Q_W  = (const float*)d_in[4];
    const float* Q_b  = (const float*)d_in[5];
    const float* V_W  = (const float*)d_in[6];
    const float* V_b  = (const float*)d_in[7];
    const float* O_W  = (const float*)d_in[8];
    const float* O_b  = (const float*)d_in[9];
    const float* ln1g = (const float*)d_in[10];
    const float* ln1b = (const float*)d_in[11];
    const float* ln2g = (const float*)d_in[12];
    const float* ln2b = (const float*)d_in[13];
    const float* W1   = (const float*)d_in[14];
    const float* b1   = (const float*)d_in[15];
    const float* W2   = (const float*)d_in[16];
    const float* b2   = (const float*)d_in[17];
    float* out = (float*)d_out;

    float *p_xs, *p_res, *p_qkv, *p_o, *p_out1, *p_h, *p_h1, *p_bqkv;
    __nv_bfloat16 *p_wqh, *p_wql, *p_woh, *p_wol, *p_w1h, *p_w1l, *p_w2h, *p_w2l;
    cudaGetSymbolAddress((void**)&p_xs, g_xs);
    cudaGetSymbolAddress((void**)&p_res, g_res);
    cudaGetSymbolAddress((void**)&p_qkv, g_qkv);
    cudaGetSymbolAddress((void**)&p_o, g_o);
    cudaGetSymbolAddress((void**)&p_out1, g_out1);
    cudaGetSymbolAddress((void**)&p_h, g_h);
    cudaGetSymbolAddress((void**)&p_h1, g_h1);
    cudaGetSymbolAddress((void**)&p_bqkv, g_bqkv);
    cudaGetSymbolAddress((void**)&p_wqh, g_wqkv_h);
    cudaGetSymbolAddress((void**)&p_wql, g_wqkv_l);
    cudaGetSymbolAddress((void**)&p_woh, g_wo_h);
    cudaGetSymbolAddress((void**)&p_wol, g_wo_l);
    cudaGetSymbolAddress((void**)&p_w1h, g_w1_h);
    cudaGetSymbolAddress((void**)&p_w1l, g_w1_l);
    cudaGetSymbolAddress((void**)&p_w2h, g_w2_h);
    cudaGetSymbolAddress((void**)&p_w2l, g_w2_l);

    cudaFuncSetAttribute(attn_kernel, cudaFuncAttributeMaxDynamicSharedMemorySize, ATT_SMEM);
    cudaFuncSetAttribute(tc_gemm<0, 0>, cudaFuncAttributeMaxDynamicSharedMemorySize, GEMM_SMEM);
    cudaFuncSetAttribute(tc_gemm<0, 1>, cudaFuncAttributeMaxDynamicSharedMemorySize, GEMM_SMEM);
    cudaFuncSetAttribute(tc_gemm<1, 0>, cudaFuncAttributeMaxDynamicSharedMemorySize, GEMM_SMEM);

    pack_qkvw<<<dim3(16, 2, 24), 256>>>(Q_W, K_W, V_W, p_wqh, p_wql);
    pack_w3<<<dim3(16, 16, 3), 256>>>(O_W, W1, W2, p_woh, p_wol, p_w1h, p_w1l, p_w2h, p_w2l);
    pack_bias<<<6, 256>>>(Q_b, K_b, V_b, p_bqkv);
    transpose_in<<<dim3(16, 256), 256>>>(x, p_xs);
    ln_rows<<<M_, 256>>>(p_xs, ln1g, ln1b, p_res);
    tc_gemm<0, 0><<<dim3(12, 64), 256, GEMM_SMEM>>>(p_res, p_wqh, p_wql, p_bqkv, nullptr, p_qkv, NQKV);
    attn_kernel<<<dim3(16, 8, 8), 256, ATT_SMEM>>>(p_qkv, p_o);
    tc_gemm<0, 1><<<dim3(4, 64), 256, GEMM_SMEM>>>(p_o, p_woh, p_wol, O_b, p_xs, p_out1, C_);
    ln_rows<<<M_, 256>>>(p_out1, ln2g, ln2b, p_h);
    tc_gemm<1, 0><<<dim3(4, 64), 256, GEMM_SMEM>>>(p_h, p_w1h, p_w1l, b1, nullptr, p_h1, C_);
    tc_gemm<0, 1><<<dim3(4, 64), 256, GEMM_SMEM>>>(p_h1, p_w2h, p_w2l, b2, p_out1, p_res, C_);
    transpose_out<<<dim3(16, 256), 256>>>(p_res, out);
}

// round 4
// speedup vs baseline: 2.0777x; 1.1269x over previous
#include <cuda_runtime.h>
#include <cuda_bf16.h>
#include <cstdint>
#include <cstddef>

#define B_ 8
#define C_ 512
#define S_ 1024
#define NH 8
#define HD 64
#define M_ (B_ * S_)   // 8192
#define NQKV 1536

// ---------------- scratch (device globals, no allocation) ----------------
__device__ float g_xs[M_ * C_];
__device__ float g_res[M_ * C_];
__device__ float g_qkv[M_ * NQKV];
__device__ float g_o[M_ * C_];
__device__ float g_out1[M_ * C_];
__device__ float g_h[M_ * C_];
__device__ float g_h1[M_ * C_];
__device__ __nv_bfloat16 g_wqkv_h[NQKV * C_];
__device__ __nv_bfloat16 g_wqkv_l[NQKV * C_];
__device__ __nv_bfloat16 g_wo_h[C_ * C_];
__device__ __nv_bfloat16 g_wo_l[C_ * C_];
__device__ __nv_bfloat16 g_w1_h[C_ * C_];
__device__ __nv_bfloat16 g_w1_l[C_ * C_];
__device__ __nv_bfloat16 g_w2_h[C_ * C_];
__device__ __nv_bfloat16 g_w2_l[C_ * C_];
__device__ float g_bqkv[NQKV];

// ---------------- PTX helpers ----------------
__device__ __forceinline__ uint32_t smem_to_u32(const void* p) {
    uint32_t a;
    asm("{ .reg .u64 t; cvta.to.shared.u64 t, %1; cvt.u32.u64 %0, t; }" : "=r"(a) : "l"(p));
    return a;
}
__device__ __forceinline__ uint32_t sw128(uint32_t off) { return off ^ ((off >> 3) & 0x70); }

// warp-level mma.sync (sm_80+ PTX, assembles on plain sm_103 target)
__device__ __forceinline__ void mma_bf16(float* c, const uint32_t* a, const uint32_t* b) {
    asm volatile(
        "mma.sync.aligned.m16n8k16.row.col.f32.bf16.bf16.f32 "
        "{%0,%1,%2,%3}, {%4,%5,%6,%7}, {%8,%9}, {%0,%1,%2,%3};"
        : "+f"(c[0]), "+f"(c[1]), "+f"(c[2]), "+f"(c[3])
        : "r"(a[0]), "r"(a[1]), "r"(a[2]), "r"(a[3]), "r"(b[0]), "r"(b[1]));
}
__device__ __forceinline__ uint32_t lds32(uint32_t addr) {
    uint32_t v;
    asm volatile("ld.shared.b32 %0, [%1];" : "=r"(v) : "r"(addr));
    return v;
}

// ---------------- small helpers ----------------
__device__ __forceinline__ float blockReduceSum(float v, float* red) {
    #pragma unroll
    for (int o = 16; o; o >>= 1) v += __shfl_xor_sync(0xffffffffu, v, o);
    int wid = threadIdx.x >> 5;
    if ((threadIdx.x & 31) == 0) red[wid] = v;
    __syncthreads();
    float r = (threadIdx.x < 8) ? red[threadIdx.x] : 0.f;
    if (threadIdx.x < 32) {
        #pragma unroll
        for (int o = 4; o; o >>= 1) r += __shfl_xor_sync(0xffffffffu, r, o);
        if (threadIdx.x == 0) red[0] = r;
    }
    __syncthreads();
    float out = red[0];
    __syncthreads();
    return out;
}

__device__ __forceinline__ void split_bf16(float v, __nv_bfloat16& h, __nv_bfloat16& l) {
    h = __float2bfloat16(v);
    l = __float2bfloat16(v - __bfloat162float(h));
}
__device__ __forceinline__ uint32_t pack_hi(float a, float b) {
    __nv_bfloat16 ha = __float2bfloat16(a), hb = __float2bfloat16(b);
    return ((uint32_t)__bfloat16_as_ushort(hb) << 16) | __bfloat16_as_ushort(ha);
}
__device__ __forceinline__ uint32_t pack_lo(float a, float b) {
    __nv_bfloat16 ha = __float2bfloat16(a), hb = __float2bfloat16(b);
    __nv_bfloat16 la = __float2bfloat16(a - __bfloat162float(ha));
    __nv_bfloat16 lb = __float2bfloat16(b - __bfloat162float(hb));
    return ((uint32_t)__bfloat16_as_ushort(lb) << 16) | __bfloat16_as_ushort(la);
}

// ---------------- pack kernels ----------------
__global__ void pack_qkvw(const float* __restrict__ QW, const float* __restrict__ KW,
                          const float* __restrict__ VW,
                          __nv_bfloat16* __restrict__ wh, __nv_bfloat16* __restrict__ wl) {
    __shared__ float t[32][33];
    int sel = blockIdx.z >> 3, n = blockIdx.z & 7;
    const float* src = sel == 0 ? QW : (sel == 1 ? KW : VW);
    int c0 = blockIdx.x * 32, d0 = blockIdx.y * 32;
    int lx = threadIdx.x & 31, ly = threadIdx.x >> 5;
    #pragma unroll
    for (int i = 0; i < 4; i++)
        t[ly + i * 8][lx] = src[((size_t)n * C_ + c0 + ly + i * 8) * HD + d0 + lx];
    __syncthreads();
    #pragma unroll
    for (int i = 0; i < 4; i++) {
        int row = sel * 512 + n * 64 + d0 + ly + i * 8;
        float v = t[lx][ly + i * 8];
        __nv_bfloat16 h, l; split_bf16(v, h, l);
        wh[(size_t)row * C_ + c0 + lx] = h;
        wl[(size_t)row * C_ + c0 + lx] = l;
    }
}
__global__ void pack_w3(const float* __restrict__ OW, const float* __restrict__ W1,
                        const float* __restrict__ W2,
                        __nv_bfloat16* __restrict__ oh, __nv_bfloat16* __restrict__ ol,
                        __nv_bfloat16* __restrict__ h1, __nv_bfloat16* __restrict__ l1,
                        __nv_bfloat16* __restrict__ h2, __nv_bfloat16* __restrict__ l2) {
    __shared__ float t[32][33];
    const float* src = blockIdx.z == 0 ? OW : (blockIdx.z == 1 ? W1 : W2);
    __nv_bfloat16* dh = blockIdx.z == 0 ? oh : (blockIdx.z == 1 ? h1 : h2);
    __nv_bfloat16* dl = blockIdx.z == 0 ? ol : (blockIdx.z == 1 ? l1 : l2);
    int n0 = blockIdx.x * 32, k0 = blockIdx.y * 32;
    int lx = threadIdx.x & 31, ly = threadIdx.x >> 5;
    #pragma unroll
    for (int i = 0; i < 4; i++)
        t[ly + i * 8][lx] = src[(size_t)(k0 + ly + i * 8) * C_ + n0 + lx];
    __syncthreads();
    #pragma unroll
    for (int i = 0; i < 4; i++) {
        int n = n0 + ly + i * 8;
        float v = t[lx][ly + i * 8];
        __nv_bfloat16 h, l; split_bf16(v, h, l);
        dh[(size_t)n * C_ + k0 + lx] = h;
        dl[(size_t)n * C_ + k0 + lx] = l;
    }
}
__global__ void pack_bias(const float* __restrict__ Qb, const float* __restrict__ Kb,
                          const float* __restrict__ Vb, float* __restrict__ b) {
    int j = blockIdx.x * blockDim.x + threadIdx.x;
    if (j < 512) b[j] = Qb[j];
    else if (j < 1024) b[j] = Kb[j - 512];
    else if (j < 1536) b[j] = Vb[j - 1024];
}

// ---------------- transposes ----------------
__global__ void transpose_in(const float* __restrict__ x, float* __restrict__ xs) {
    __shared__ float t[32][33];
    int c0 = blockIdx.x * 32, r0 = blockIdx.y * 32;
    int b = r0 >> 10, s0 = r0 & 1023;
    int lx = threadIdx.x & 31, ly = threadIdx.x >> 5;
    #pragma unroll
    for (int i = 0; i < 4; i++)
        t[ly + i * 8][lx] = x[((size_t)b * C_ + c0 + ly + i * 8) * S_ + s0 + lx];
    __syncthreads();
    #pragma unroll
    for (int i = 0; i < 4; i++)
        xs[(size_t)(r0 + ly + i * 8) * C_ + c0 + lx] = t[lx][ly + i * 8];
}
__global__ void transpose_out(const float* __restrict__ in, float* __restrict__ out) {
    __shared__ float t[32][33];
    int c0 = blockIdx.x * 32, r0 = blockIdx.y * 32;
    int b = r0 >> 10, s0 = r0 & 1023;
    int lx = threadIdx.x & 31, ly = threadIdx.x >> 5;
    #pragma unroll
    for (int i = 0; i < 4; i++)
        t[ly + i * 8][lx] = in[(size_t)(r0 + ly + i * 8) * C_ + c0 + lx];
    __syncthreads();
    #pragma unroll
    for (int i = 0; i < 4; i++)
        out[((size_t)b * C_ + c0 + ly + i * 8) * S_ + s0 + lx] = t[lx][ly + i * 8];
}

// ---------------- LayerNorm over rows ----------------
__global__ void ln_rows(const float* __restrict__ in, const float* __restrict__ g,
                        const float* __restrict__ bt, float* __restrict__ res) {
    int row = blockIdx.x;
    int tid = threadIdx.x;
    __shared__ float red[8];
    const float* xp = in + (size_t)row * C_;
    float v1 = xp[tid];
    float v2 = xp[tid + 256];
    float sum = blockReduceSum(v1 + v2, red);
    float mu = sum * (1.f / 512.f);
    float d1 = v1 - mu, d2 = v2 - mu;
    float var = blockReduceSum(d1 * d1 + d2 * d2, red) * (1.f / 512.f);
    float rstd = rsqrtf(var + 1e-5f);
    size_t ro = (size_t)row * C_;
    res[ro + tid] = d1 * rstd * g[tid] + bt[tid];
    res[ro + tid + 256] = d2 * rstd * g[tid + 256] + bt[tid + 256];
}

// ---------------- tensor-core GEMM (mma.sync bf16x3): C = A(Mx512)*B^T + bias [gelu] [+resid]
static constexpr int SM_AH = 1024;
static constexpr int SM_AL = SM_AH + 16384;
static constexpr int SM_BH = SM_AL + 16384;
static constexpr int SM_BL = SM_BH + 16384;
static constexpr int GEMM_SMEM = SM_BL + 16384;   // 66560

template <int ACT, int RESID>
__global__ void __launch_bounds__(256, 2)
tc_gemm(const float* __restrict__ A, const __nv_bfloat16* __restrict__ Bh,
        const __nv_bfloat16* __restrict__ Bl, const float* __restrict__ bias,
        const float* __restrict__ resid, float* __restrict__ Cout, int ld_out) {
    extern __shared__ char smem[];
    uint32_t sb = smem_to_u32(smem);
    int tid = threadIdx.x;
    int wid = tid >> 5;
    int lid = tid & 31;
    int col0 = blockIdx.x * 128;
    int row0 = blockIdx.y * 128;

    float acc[2][8][4] = {};   // [m-frag][n-tile][regs]
    int grp = lid >> 2;
    int qd = lid & 3;
    int wr = wid >> 1;         // 0..3 -> m offset
    int wc = wid & 1;          // 0..1 -> n offset
    int m_base = wr * 32;
    int n_base = wc * 64;

    for (int c = 0; c < 8; c++) {
        int k0 = c * 64;
        // A tile: 128 rows x 64 fp32 -> bf16 hi/lo swizzled
        #pragma unroll
        for (int it = 0; it < 8; it++) {
            int f = tid + 256 * it;
            int r = f >> 4;
            int c4 = (f & 15) * 4;
            float4 av = *(const float4*)(A + (size_t)(row0 + r) * C_ + k0 + c4);
            uint32_t off = sw128((uint32_t)(r * 128 + c4 * 2));
            *(uint2*)(smem + SM_AH + off) = make_uint2(pack_hi(av.x, av.y), pack_hi(av.z, av.w));
            *(uint2*)(smem + SM_AL + off) = make_uint2(pack_lo(av.x, av.y), pack_lo(av.z, av.w));
        }
        // B tiles: 128 rows x 64 bf16 (128B rows)
        #pragma unroll
        for (int it = 0; it < 4; it++) {
            int f = tid + 256 * it;
            int r = f >> 3;
            int u = f & 7;
            size_t gi = (size_t)(col0 + r) * C_ + k0 + u * 8;
            uint32_t off = sw128((uint32_t)(r * 128 + u * 16));
            *(uint4*)(smem + SM_BH + off) = *(const uint4*)(Bh + gi);
            *(uint4*)(smem + SM_BL + off) = *(const uint4*)(Bl + gi);
        }
        __syncthreads();
        #pragma unroll
        for (int ks = 0; ks < 4; ks++) {
            int kk = ks * 16 + qd * 2;
            uint32_t ah[2][4], al[2][4];
            #pragma unroll
            for (int f2 = 0; f2 < 2; f2++) {
                int m = m_base + f2 * 16 + grp;
                uint32_t o00 = sw128((uint32_t)(m * 128 + kk * 2));
                uint32_t o10 = sw128((uint32_t)((m + 8) * 128 + kk * 2));
                uint32_t o01 = sw128((uint32_t)(m * 128 + (kk + 8) * 2));
                uint32_t o11 = sw128((uint32_t)((m + 8) * 128 + (kk + 8) * 2));
                ah[f2][0] = lds32(sb + SM_AH + o00); ah[f2][1] = lds32(sb + SM_AH + o10);
                ah[f2][2] = lds32(sb + SM_AH + o01); ah[f2][3] = lds32(sb + SM_AH + o11);
                al[f2][0] = lds32(sb + SM_AL + o00); al[f2][1] = lds32(sb + SM_AL + o10);
                al[f2][2] = lds32(sb + SM_AL + o01); al[f2][3] = lds32(sb + SM_AL + o11);
            }
            #pragma unroll
            for (int t = 0; t < 8; t++) {
                int n = n_base + t * 8 + grp;
                uint32_t o0 = sw128((uint32_t)(n * 128 + kk * 2));
                uint32_t o1 = sw128((uint32_t)(n * 128 + (kk + 8) * 2));
                uint32_t bh[2], bl[2];
                bh[0] = lds32(sb + SM_BH + o0); bh[1] = lds32(sb + SM_BH + o1);
                bl[0] = lds32(sb + SM_BL + o0); bl[1] = lds32(sb + SM_BL + o1);
                #pragma unroll
                for (int f2 = 0; f2 < 2; f2++) {
                    mma_bf16(acc[f2][t], ah[f2], bh);
                    mma_bf16(acc[f2][t], ah[f2], bl);
                    mma_bf16(acc[f2][t], al[f2], bh);
                }
            }
        }
        __syncthreads();
    }

    // register-direct epilogue
    #pragma unroll
    for (int f2 = 0; f2 < 2; f2++) {
        #pragma unroll
        for (int rr = 0; rr < 2; rr++) {
            int r = row0 + m_base + f2 * 16 + grp + rr * 8;
            #pragma unroll
            for (int t = 0; t < 8; t++) {
                int col = col0 + n_base + t * 8 + qd * 2;
                float v0 = acc[f2][t][rr * 2 + 0] + bias[col];
                float v1 = acc[f2][t][rr * 2 + 1] + bias[col + 1];
                if (ACT == 1) {
                    v0 = 0.5f * v0 * (1.f + erff(v0 * 0.7071067811865476f));
                    v1 = 0.5f * v1 * (1.f + erff(v1 * 0.7071067811865476f));
                }
                if (RESID) {
                    float2 rv = *(const float2*)(resid + (size_t)r * C_ + col);
                    v0 += rv.x; v1 += rv.y;
                }
                *(float2*)(Cout + (size_t)r * ld_out + col) = make_float2(v0, v1);
            }
        }
    }
}

// ---------------- flash attention on mma.sync (128q block, 64k tiles, bf16x3) ----------------
// SMEM: QH 16K | QL 16K | KH 8K | KL 8K | VH 8K | VL 8K = 64K
static constexpr int ATT_QH = 0;
static constexpr int ATT_QL = 16384;
static constexpr int ATT_KH = 32768;
static constexpr int ATT_KL = 40960;
static constexpr int ATT_VH = 49152;
static constexpr int ATT_VL = 57344;
static constexpr int ATT_SMEM = 65536;

__global__ void __launch_bounds__(256, 2)
attn_mma(const float* __restrict__ qkv, float* __restrict__ o) {
    extern __shared__ char smem[];
    uint32_t sb = smem_to_u32(smem);
    const uint32_t QH = sb + ATT_QH, QL = sb + ATT_QL, KH = sb + ATT_KH,
                   KL = sb + ATT_KL, VH = sb + ATT_VH, VL = sb + ATT_VL;
    int tid = threadIdx.x;
    int wid = tid >> 5, lid = tid & 31;
    int grp = lid >> 2, qd = lid & 3;
    int qt = blockIdx.x, n = blockIdx.y, b = blockIdx.z;
    size_t qbase = ((size_t)(b * S_ + qt * 128)) * NQKV + n * HD;
    size_t obase = ((size_t)(b * S_ + qt * 128)) * C_ + n * HD;
    const float scale = 0.04419417382415922f;   // 1/sqrt(512)

    // load Q (pre-scaled) -> bf16 hi/lo, swizzled [row][d]
    #pragma unroll
    for (int it = 0; it < 8; it++) {
        int f = tid + 256 * it;
        int r = f >> 4, c4 = (f & 15) * 4;
        float4 v4 = *(const float4*)(qkv + qbase + (size_t)r * NQKV + c4);
        v4.x *= scale; v4.y *= scale; v4.z *= scale; v4.w *= scale;
        uint32_t off = sw128((uint32_t)(r * 128 + c4 * 2));
        *(uint2*)(smem + ATT_QH + off) = make_uint2(pack_hi(v4.x, v4.y), pack_hi(v4.z, v4.w));
        *(uint2*)(smem + ATT_QL + off) = make_uint2(pack_lo(v4.x, v4.y), pack_lo(v4.z, v4.w));
    }

    float Oa[8][4] = {};
    float m0 = -1e30f, m1 = -1e30f, l0 = 0.f, l1 = 0.f;
    int r0 = wid * 16;

    for (int kt = 0; kt < 16; kt++) {
        __syncthreads();
        size_t kb = ((size_t)(b * S_ + kt * 64)) * NQKV + n * HD + 512;
        #pragma unroll
        for (int it = 0; it < 4; it++) {
            int f = tid + 256 * it;
            int r = f >> 4, c4 = (f & 15) * 4;
            float4 kv4 = *(const float4*)(qkv + kb + (size_t)r * NQKV + c4);
            uint32_t off = sw128((uint32_t)(r * 128 + c4 * 2));
            *(uint2*)(smem + ATT_KH + off) = make_uint2(pack_hi(kv4.x, kv4.y), pack_hi(kv4.z, kv4.w));
            *(uint2*)(smem + ATT_KL + off) = make_uint2(pack_lo(kv4.x, kv4.y), pack_lo(kv4.z, kv4.w));
            // V transposed: Vt[d][key]
            float4 vv4 = *(const float4*)(qkv + kb + 512 + (size_t)r * NQKV + c4);
            float vj[4] = {vv4.x, vv4.y, vv4.z, vv4.w};
            #pragma unroll
            for (int j = 0; j < 4; j++) {
                __nv_bfloat16 h, l; split_bf16(vj[j], h, l);
                uint32_t toff = sw128((uint32_t)((c4 + j) * 128 + r * 2));
                *(__nv_bfloat16*)(smem + ATT_VH + toff) = h;
                *(__nv_bfloat16*)(smem + ATT_VL + toff) = l;
            }
        }
        __syncthreads();

        // S = Q K^T  (scores already scaled via Q)
        float Sc[8][4];
        #pragma unroll
        for (int nf = 0; nf < 8; nf++)
            Sc[nf][0] = Sc[nf][1] = Sc[nf][2] = Sc[nf][3] = 0.f;
        #pragma unroll
        for (int ks = 0; ks < 4; ks++) {
            int kq = ks * 16 + qd * 2;
            int rA = r0 + grp;
            uint32_t oa0 = sw128((uint32_t)(rA * 128 + kq * 2));
            uint32_t oa1 = sw128((uint32_t)((rA + 8) * 128 + kq * 2));
            uint32_t oa2 = sw128((uint32_t)(rA * 128 + (kq + 8) * 2));
            uint32_t oa3 = sw128((uint32_t)((rA + 8) * 128 + (kq + 8) * 2));
            uint32_t ah[4] = {lds32(QH + oa0), lds32(QH + oa1), lds32(QH + oa2), lds32(QH + oa3)};
            uint32_t al[4] = {lds32(QL + oa0), lds32(QL + oa1), lds32(QL + oa2), lds32(QL + oa3)};
            #pragma unroll
            for (int nf = 0; nf < 8; nf++) {
                int nn = nf * 8 + grp;
                uint32_t ob0 = sw128((uint32_t)(nn * 128 + kq * 2));
                uint32_t ob1 = sw128((uint32_t)(nn * 128 + (kq + 8) * 2));
                uint32_t bh[2] = {lds32(KH + ob0), lds32(KH + ob1)};
                uint32_t bl[2] = {lds32(KL + ob0), lds32(KL + ob1)};
                mma_bf16(Sc[nf], ah, bh);
                mma_bf16(Sc[nf], ah, bl);
                mma_bf16(Sc[nf], al, bh);
            }
        }

        // warp-local online softmax (rows r0+grp and r0+grp+8)
        float mx0 = -1e30f, mx1 = -1e30f;
        #pragma unroll
        for (int nf = 0; nf < 8; nf++) {
            mx0 = fmaxf(mx0, fmaxf(Sc[nf][0], Sc[nf][1]));
            mx1 = fmaxf(mx1, fmaxf(Sc[nf][2], Sc[nf][3]));
        }
        mx0 = fmaxf(mx0, __shfl_xor_sync(0xffffffffu, mx0, 1));
        mx0 = fmaxf(mx0, __shfl_xor_sync(0xffffffffu, mx0, 2));
        mx1 = fmaxf(mx1, __shfl_xor_sync(0xffffffffu, mx1, 1));
        mx1 = fmaxf(mx1, __shfl_xor_sync(0xffffffffu, mx1, 2));
        float mn0 = fmaxf(m0, mx0), mn1 = fmaxf(m1, mx1);
        float al0 = __expf(m0 - mn0), al1 = __expf(m1 - mn1);
        float s0 = 0.f, s1 = 0.f;
        #pragma unroll
        for (int nf = 0; nf < 8; nf++) {
            Sc[nf][0] = __expf(Sc[nf][0] - mn0);
            Sc[nf][1] = __expf(Sc[nf][1] - mn0);
            Sc[nf][2] = __expf(Sc[nf][2] - mn1);
            Sc[nf][3] = __expf(Sc[nf][3] - mn1);
            s0 += Sc[nf][0] + Sc[nf][1];
            s1 += Sc[nf][2] + Sc[nf][3];
        }
        s0 += __shfl_xor_sync(0xffffffffu, s0, 1);
        s0 += __shfl_xor_sync(0xffffffffu, s0, 2);
        s1 += __shfl_xor_sync(0xffffffffu, s1, 1);
        s1 += __shfl_xor_sync(0xffffffffu, s1, 2);
        l0 = l0 * al0 + s0;
        l1 = l1 * al1 + s1;
        m0 = mn0; m1 = mn1;
        #pragma unroll
        for (int nf = 0; nf < 8; nf++) {
            Oa[nf][0] *= al0; Oa[nf][1] *= al0;
            Oa[nf][2] *= al1; Oa[nf][3] *= al1;
        }

        // O += P V  (P in registers: C-frag layout == A-frag layout)
        #pragma unroll
        for (int t = 0; t < 4; t++) {
            uint32_t pah[4], pal[4];
            pah[0] = pack_hi(Sc[2 * t][0], Sc[2 * t][1]);
            pah[1] = pack_hi(Sc[2 * t][2], Sc[2 * t][3]);
            pah[2] = pack_hi(Sc[2 * t + 1][0], Sc[2 * t + 1][1]);
            pah[3] = pack_hi(Sc[2 * t + 1][2], Sc[2 * t + 1][3]);
            pal[0] = pack_lo(Sc[2 * t][0], Sc[2 * t][1]);
            pal[1] = pack_lo(Sc[2 * t][2], Sc[2 * t][3]);
            pal[2] = pack_lo(Sc[2 * t + 1][0], Sc[2 * t + 1][1]);
            pal[3] = pack_lo(Sc[2 * t + 1][2], Sc[2 * t + 1][3]);
            int kq = t * 16 + qd * 2;
            #pragma unroll
            for (int nf = 0; nf < 8; nf++) {
                int nn = nf * 8 + grp;
                uint32_t ob0 = sw128((uint32_t)(nn * 128 + kq * 2));
                uint32_t ob1 = sw128((uint32_t)(nn * 128 + (kq + 8) * 2));
                uint32_t bh[2] = {lds32(VH + ob0), lds32(VH + ob1)};
                uint32_t bl[2] = {lds32(VL + ob0), lds32(VL + ob1)};
                mma_bf16(Oa[nf], pah, bh);
                mma_bf16(Oa[nf], pal, bh);
                mma_bf16(Oa[nf], pah, bl);
            }
        }
    }

    float li0 = 1.f / l0, li1 = 1.f / l1;
    int r = r0 + grp;
    #pragma unroll
    for (int nf = 0; nf < 8; nf++) {
        int col = nf * 8 + qd * 2;
        *(float2*)(o + obase + (size_t)r * C_ + col) =
            make_float2(Oa[nf][0] * li0, Oa[nf][1] * li0);
        *(float2*)(o + obase + (size_t)(r + 8) * C_ + col) =
            make_float2(Oa[nf][2] * li1, Oa[nf][3] * li1);
    }
}

// ---------------- launch ----------------
extern "C" void kernel_launch(void* const* d_in, const int* in_sizes, int n_in,
                              void* d_out, int out_size) {
    (void)in_sizes; (void)n_in; (void)out_size;
    const float* x    = (const float*)d_in[0];
    const float* K_W  = (const float*)d_in[2];
    const float* K_b  = (const float*)d_in[3];
    const float* Q_W  = (const float*)d_in[4];
    const float* Q_b  = (const float*)d_in[5];
    const float* V_W  = (const float*)d_in[6];
    const float* V_b  = (const float*)d_in[7];
    const float* O_W  = (const float*)d_in[8];
    const float* O_b  = (const float*)d_in[9];
    const float* ln1g = (const float*)d_in[10];
    const float* ln1b = (const float*)d_in[11];
    const float* ln2g = (const float*)d_in[12];
    const float* ln2b = (const float*)d_in[13];
    const float* W1   = (const float*)d_in[14];
    const float* b1   = (const float*)d_in[15];
    const float* W2   = (const float*)d_in[16];
    const float* b2   = (const float*)d_in[17];
    float* out = (float*)d_out;

    float *p_xs, *p_res, *p_qkv, *p_o, *p_out1, *p_h, *p_h1, *p_bqkv;
    __nv_bfloat16 *p_wqh, *p_wql, *p_woh, *p_wol, *p_w1h, *p_w1l, *p_w2h, *p_w2l;
    cudaGetSymbolAddress((void**)&p_xs, g_xs);
    cudaGetSymbolAddress((void**)&p_res, g_res);
    cudaGetSymbolAddress((void**)&p_qkv, g_qkv);
    cudaGetSymbolAddress((void**)&p_o, g_o);
    cudaGetSymbolAddress((void**)&p_out1, g_out1);
    cudaGetSymbolAddress((void**)&p_h, g_h);
    cudaGetSymbolAddress((void**)&p_h1, g_h1);
    cudaGetSymbolAddress((void**)&p_bqkv, g_bqkv);
    cudaGetSymbolAddress((void**)&p_wqh, g_wqkv_h);
    cudaGetSymbolAddress((void**)&p_wql, g_wqkv_l);
    cudaGetSymbolAddress((void**)&p_woh, g_wo_h);
    cudaGetSymbolAddress((void**)&p_wol, g_wo_l);
    cudaGetSymbolAddress((void**)&p_w1h, g_w1_h);
    cudaGetSymbolAddress((void**)&p_w1l, g_w1_l);
    cudaGetSymbolAddress((void**)&p_w2h, g_w2_h);
    cudaGetSymbolAddress((void**)&p_w2l, g_w2_l);

    cudaFuncSetAttribute(attn_mma, cudaFuncAttributeMaxDynamicSharedMemorySize, ATT_SMEM);
    cudaFuncSetAttribute(tc_gemm<0, 0>, cudaFuncAttributeMaxDynamicSharedMemorySize, GEMM_SMEM);
    cudaFuncSetAttribute(tc_gemm<0, 1>, cudaFuncAttributeMaxDynamicSharedMemorySize, GEMM_SMEM);
    cudaFuncSetAttribute(tc_gemm<1, 0>, cudaFuncAttributeMaxDynamicSharedMemorySize, GEMM_SMEM);

    pack_qkvw<<<dim3(16, 2, 24), 256>>>(Q_W, K_W, V_W, p_wqh, p_wql);
    pack_w3<<<dim3(16, 16, 3), 256>>>(O_W, W1, W2, p_woh, p_wol, p_w1h, p_w1l, p_w2h, p_w2l);
    pack_bias<<<6, 256>>>(Q_b, K_b, V_b, p_bqkv);
    transpose_in<<<dim3(16, 256), 256>>>(x, p_xs);
    ln_rows<<<M_, 256>>>(p_xs, ln1g, ln1b, p_res);
    tc_gemm<0, 0><<<dim3(12, 64), 256, GEMM_SMEM>>>(p_res, p_wqh, p_wql, p_bqkv, nullptr, p_qkv, NQKV);
    attn_mma<<<dim3(8, 8, 8), 256, ATT_SMEM>>>(p_qkv, p_o);
    tc_gemm<0, 1><<<dim3(4, 64), 256, GEMM_SMEM>>>(p_o, p_woh, p_wol, O_b, p_xs, p_out1, C_);
    ln_rows<<<M_, 256>>>(p_out1, ln2g, ln2b, p_h);
    tc_gemm<1, 0><<<dim3(4, 64), 256, GEMM_SMEM>>>(p_h, p_w1h, p_w1l, b1, nullptr, p_h1, C_);
    tc_gemm<0, 1><<<dim3(4, 64), 256, GEMM_SMEM>>>(p_h1, p_w2h, p_w2l, b2, p_out1, p_res, C_);
    transpose_out<<<dim3(16, 256), 256>>>(p_res, out);
}

// round 5
// speedup vs baseline: 2.7434x; 1.3204x over previous
#include <cuda_runtime.h>
#include <cuda_bf16.h>
#include <cstdint>
#include <cstddef>

#define B_ 8
#define C_ 512
#define S_ 1024
#define NH 8
#define HD 64
#define M_ (B_ * S_)   // 8192
#define NQKV 1536

// ---------------- scratch (device globals, no allocation) ----------------
__device__ __align__(16) float g_xs[M_ * C_];
__device__ __align__(16) float g_out1[M_ * C_];
__device__ __align__(16) float g_fin[M_ * C_];
__device__ __align__(16) __nv_bfloat16 g_res_h[M_ * C_];
__device__ __align__(16) __nv_bfloat16 g_res_l[M_ * C_];
__device__ __align__(16) __nv_bfloat16 g_qkv_h[M_ * NQKV];
__device__ __align__(16) __nv_bfloat16 g_qkv_l[M_ * NQKV];
__device__ __align__(16) __nv_bfloat16 g_o_h[M_ * C_];
__device__ __align__(16) __nv_bfloat16 g_o_l[M_ * C_];
__device__ __align__(16) __nv_bfloat16 g_h_h[M_ * C_];
__device__ __align__(16) __nv_bfloat16 g_h_l[M_ * C_];
__device__ __align__(16) __nv_bfloat16 g_h1_h[M_ * C_];
__device__ __align__(16) __nv_bfloat16 g_h1_l[M_ * C_];
__device__ __align__(16) __nv_bfloat16 g_wqkv_h[NQKV * C_];
__device__ __align__(16) __nv_bfloat16 g_wqkv_l[NQKV * C_];
__device__ __align__(16) __nv_bfloat16 g_wo_h[C_ * C_];
__device__ __align__(16) __nv_bfloat16 g_wo_l[C_ * C_];
__device__ __align__(16) __nv_bfloat16 g_w1_h[C_ * C_];
__device__ __align__(16) __nv_bfloat16 g_w1_l[C_ * C_];
__device__ __align__(16) __nv_bfloat16 g_w2_h[C_ * C_];
__device__ __align__(16) __nv_bfloat16 g_w2_l[C_ * C_];
__device__ float g_bqkv[NQKV];

// ---------------- PTX helpers (all sm_80-level, valid on plain sm_103) ----------------
__device__ __forceinline__ uint32_t smem_to_u32(const void* p) {
    uint32_t a;
    asm("{ .reg .u64 t; cvta.to.shared.u64 t, %1; cvt.u32.u64 %0, t; }" : "=r"(a) : "l"(p));
    return a;
}
__device__ __forceinline__ uint32_t sw128(uint32_t off) { return off ^ ((off >> 3) & 0x70); }

__device__ __forceinline__ void mma_bf16(float* c, const uint32_t* a, const uint32_t* b) {
    asm volatile(
        "mma.sync.aligned.m16n8k16.row.col.f32.bf16.bf16.f32 "
        "{%0,%1,%2,%3}, {%4,%5,%6,%7}, {%8,%9}, {%0,%1,%2,%3};"
        : "+f"(c[0]), "+f"(c[1]), "+f"(c[2]), "+f"(c[3])
        : "r"(a[0]), "r"(a[1]), "r"(a[2]), "r"(a[3]), "r"(b[0]), "r"(b[1]));
}
__device__ __forceinline__ void ldsm_x4(uint32_t* r, uint32_t addr) {
    asm volatile("ldmatrix.sync.aligned.m8n8.x4.shared.b16 {%0,%1,%2,%3}, [%4];"
        : "=r"(r[0]), "=r"(r[1]), "=r"(r[2]), "=r"(r[3]) : "r"(addr));
}
__device__ __forceinline__ void ldsm_x4_t(uint32_t* r, uint32_t addr) {
    asm volatile("ldmatrix.sync.aligned.m8n8.x4.trans.shared.b16 {%0,%1,%2,%3}, [%4];"
        : "=r"(r[0]), "=r"(r[1]), "=r"(r[2]), "=r"(r[3]) : "r"(addr));
}
#define CP_ASYNC16(dst, src) \
    asm volatile("cp.async.cg.shared.global [%0], [%1], 16;" :: "r"(dst), "l"(src))
#define CP_COMMIT() asm volatile("cp.async.commit_group;" ::: "memory")
#define CP_WAIT1() asm volatile("cp.async.wait_group 1;" ::: "memory")
#define CP_WAIT0() asm volatile("cp.async.wait_group 0;" ::: "memory")

// ---------------- small helpers ----------------
__device__ __forceinline__ float blockReduceSum(float v, float* red) {
    #pragma unroll
    for (int o = 16; o; o >>= 1) v += __shfl_xor_sync(0xffffffffu, v, o);
    int wid = threadIdx.x >> 5;
    if ((threadIdx.x & 31) == 0) red[wid] = v;
    __syncthreads();
    float r = (threadIdx.x < 8) ? red[threadIdx.x] : 0.f;
    if (threadIdx.x < 32) {
        #pragma unroll
        for (int o = 4; o; o >>= 1) r += __shfl_xor_sync(0xffffffffu, r, o);
        if (threadIdx.x == 0) red[0] = r;
    }
    __syncthreads();
    float out = red[0];
    __syncthreads();
    return out;
}
__device__ __forceinline__ void split_bf16(float v, __nv_bfloat16& h, __nv_bfloat16& l) {
    h = __float2bfloat16(v);
    l = __float2bfloat16(v - __bfloat162float(h));
}
__device__ __forceinline__ uint32_t pack_hi(float a, float b) {
    __nv_bfloat16 ha = __float2bfloat16(a), hb = __float2bfloat16(b);
    return ((uint32_t)__bfloat16_as_ushort(hb) << 16) | __bfloat16_as_ushort(ha);
}
__device__ __forceinline__ uint32_t pack_lo(float a, float b) {
    __nv_bfloat16 ha = __float2bfloat16(a), hb = __float2bfloat16(b);
    __nv_bfloat16 la = __float2bfloat16(a - __bfloat162float(ha));
    __nv_bfloat16 lb = __float2bfloat16(b - __bfloat162float(hb));
    return ((uint32_t)__bfloat16_as_ushort(lb) << 16) | __bfloat16_as_ushort(la);
}

// ---------------- pack kernels ----------------
// QKV weights (n,c,d) -> B[(sel*512 + n*64 + d)][c] bf16 hi/lo; Q scaled by 1/sqrt(512)
__global__ void pack_qkvw(const float* __restrict__ QW, const float* __restrict__ KW,
                          const float* __restrict__ VW,
                          __nv_bfloat16* __restrict__ wh, __nv_bfloat16* __restrict__ wl) {
    __shared__ float t[32][33];
    int sel = blockIdx.z >> 3, n = blockIdx.z & 7;
    const float* src = sel == 0 ? QW : (sel == 1 ? KW : VW);
    float sc = sel == 0 ? 0.04419417382415922f : 1.f;
    int c0 = blockIdx.x * 32, d0 = blockIdx.y * 32;
    int lx = threadIdx.x & 31, ly = threadIdx.x >> 5;
    #pragma unroll
    for (int i = 0; i < 4; i++)
        t[ly + i * 8][lx] = src[((size_t)n * C_ + c0 + ly + i * 8) * HD + d0 + lx] * sc;
    __syncthreads();
    #pragma unroll
    for (int i = 0; i < 4; i++) {
        int row = sel * 512 + n * 64 + d0 + ly + i * 8;
        float v = t[lx][ly + i * 8];
        __nv_bfloat16 h, l; split_bf16(v, h, l);
        wh[(size_t)row * C_ + c0 + lx] = h;
        wl[(size_t)row * C_ + c0 + lx] = l;
    }
}
__global__ void pack_w3(const float* __restrict__ OW, const float* __restrict__ W1,
                        const float* __restrict__ W2,
                        __nv_bfloat16* __restrict__ oh, __nv_bfloat16* __restrict__ ol,
                        __nv_bfloat16* __restrict__ h1, __nv_bfloat16* __restrict__ l1,
                        __nv_bfloat16* __restrict__ h2, __nv_bfloat16* __restrict__ l2) {
    __shared__ float t[32][33];
    const float* src = blockIdx.z == 0 ? OW : (blockIdx.z == 1 ? W1 : W2);
    __nv_bfloat16* dh = blockIdx.z == 0 ? oh : (blockIdx.z == 1 ? h1 : h2);
    __nv_bfloat16* dl = blockIdx.z == 0 ? ol : (blockIdx.z == 1 ? l1 : l2);
    int n0 = blockIdx.x * 32, k0 = blockIdx.y * 32;
    int lx = threadIdx.x & 31, ly = threadIdx.x >> 5;
    #pragma unroll
    for (int i = 0; i < 4; i++)
        t[ly + i * 8][lx] = src[(size_t)(k0 + ly + i * 8) * C_ + n0 + lx];
    __syncthreads();
    #pragma unroll
    for (int i = 0; i < 4; i++) {
        int n = n0 + ly + i * 8;
        float v = t[lx][ly + i * 8];
        __nv_bfloat16 h, l; split_bf16(v, h, l);
        dh[(size_t)n * C_ + k0 + lx] = h;
        dl[(size_t)n * C_ + k0 + lx] = l;
    }
}
__global__ void pack_bias(const float* __restrict__ Qb, const float* __restrict__ Kb,
                          const float* __restrict__ Vb, float* __restrict__ b) {
    int j = blockIdx.x * blockDim.x + threadIdx.x;
    if (j < 512) b[j] = Qb[j] * 0.04419417382415922f;
    else if (j < 1024) b[j] = Kb[j - 512];
    else if (j < 1536) b[j] = Vb[j - 1024];
}

// ---------------- transposes ----------------
__global__ void transpose_in(const float* __restrict__ x, float* __restrict__ xs) {
    __shared__ float t[32][33];
    int c0 = blockIdx.x * 32, r0 = blockIdx.y * 32;
    int b = r0 >> 10, s0 = r0 & 1023;
    int lx = threadIdx.x & 31, ly = threadIdx.x >> 5;
    #pragma unroll
    for (int i = 0; i < 4; i++)
        t[ly + i * 8][lx] = x[((size_t)b * C_ + c0 + ly + i * 8) * S_ + s0 + lx];
    __syncthreads();
    #pragma unroll
    for (int i = 0; i < 4; i++)
        xs[(size_t)(r0 + ly + i * 8) * C_ + c0 + lx] = t[lx][ly + i * 8];
}
__global__ void transpose_out(const float* __restrict__ in, float* __restrict__ out) {
    __shared__ float t[32][33];
    int c0 = blockIdx.x * 32, r0 = blockIdx.y * 32;
    int b = r0 >> 10, s0 = r0 & 1023;
    int lx = threadIdx.x & 31, ly = threadIdx.x >> 5;
    #pragma unroll
    for (int i = 0; i < 4; i++)
        t[ly + i * 8][lx] = in[(size_t)(r0 + ly + i * 8) * C_ + c0 + lx];
    __syncthreads();
    #pragma unroll
    for (int i = 0; i < 4; i++)
        out[((size_t)b * C_ + c0 + ly + i * 8) * S_ + s0 + lx] = t[lx][ly + i * 8];
}

// ---------------- LayerNorm -> bf16 hi/lo ----------------
__global__ void ln_rows_hl(const float* __restrict__ in, const float* __restrict__ g,
                           const float* __restrict__ bt,
                           __nv_bfloat16* __restrict__ oh, __nv_bfloat16* __restrict__ ol) {
    int row = blockIdx.x;
    int tid = threadIdx.x;   // 256
    __shared__ float red[8];
    const float* xp = in + (size_t)row * C_;
    float2 v = *(const float2*)(xp + tid * 2);
    float sum = blockReduceSum(v.x + v.y, red);
    float mu = sum * (1.f / 512.f);
    float d1 = v.x - mu, d2 = v.y - mu;
    float var = blockReduceSum(d1 * d1 + d2 * d2, red) * (1.f / 512.f);
    float rstd = rsqrtf(var + 1e-5f);
    float y1 = d1 * rstd * g[2 * tid] + bt[2 * tid];
    float y2 = d2 * rstd * g[2 * tid + 1] + bt[2 * tid + 1];
    *(uint32_t*)(oh + (size_t)row * C_ + 2 * tid) = pack_hi(y1, y2);
    *(uint32_t*)(ol + (size_t)row * C_ + 2 * tid) = pack_lo(y1, y2);
}

// ---------------- GEMM: C = A(Mx512)*B^T + bias [gelu] [+resid]; A,B bf16 hi/lo in gmem
// tile 128x128, K-chunk 32 (interleaved hi|lo 128B rows), 2-stage cp.async, ldmatrix frags.
static constexpr int GEMM_SMEM = 65536;

template <int ACT, int RESID, int OUTHL>
__global__ void __launch_bounds__(256)
tc_gemm2(const __nv_bfloat16* __restrict__ Ah, const __nv_bfloat16* __restrict__ Al,
         const __nv_bfloat16* __restrict__ Bh, const __nv_bfloat16* __restrict__ Bl,
         const float* __restrict__ bias, const float* __restrict__ resid,
         float* __restrict__ outf, __nv_bfloat16* __restrict__ outh,
         __nv_bfloat16* __restrict__ outl, int ldo) {
    extern __shared__ char smem[];
    uint32_t sb = smem_to_u32(smem);
    int tid = threadIdx.x, wid = tid >> 5, lid = tid & 31;
    int col0 = blockIdx.x * 128, row0 = blockIdx.y * 128;
    int grp = lid >> 2, qd = lid & 3;
    int m_base = (wid >> 1) * 32, n_base = (wid & 1) * 64;
    float acc[2][8][4] = {};

    auto issue = [&](int c) {
        int k0 = c * 32;
        uint32_t st = sb + (uint32_t)(c & 1) * 32768;
        #pragma unroll
        for (int it = 0; it < 4; it++) {
            int idx = tid + it * 256;
            int hl = idx >> 9, rem = idx & 511, r = rem >> 2, u = rem & 3;
            const __nv_bfloat16* src = (hl ? Al : Ah) + (size_t)(row0 + r) * C_ + k0 + u * 8;
            CP_ASYNC16(st + sw128((uint32_t)(r * 128 + hl * 64 + u * 16)), src);
        }
        #pragma unroll
        for (int it = 0; it < 4; it++) {
            int idx = tid + it * 256;
            int hl = idx >> 9, rem = idx & 511, r = rem >> 2, u = rem & 3;
            const __nv_bfloat16* src = (hl ? Bl : Bh) + (size_t)(col0 + r) * C_ + k0 + u * 8;
            CP_ASYNC16(st + 16384u + sw128((uint32_t)(r * 128 + hl * 64 + u * 16)), src);
        }
    };
    issue(0); CP_COMMIT();
    for (int c = 0; c < 16; c++) {
        if (c < 15) { issue(c + 1); CP_COMMIT(); CP_WAIT1(); }
        else { CP_WAIT0(); }
        __syncthreads();
        uint32_t Ab = sb + (uint32_t)(c & 1) * 32768, Bb = Ab + 16384u;
        #pragma unroll
        for (int ks = 0; ks < 2; ks++) {
            uint32_t ah[2][4], al[2][4];
            #pragma unroll
            for (int f2 = 0; f2 < 2; f2++) {
                int r = m_base + f2 * 16 + (lid & 15);
                int u = ks * 2 + (lid >> 4);
                ldsm_x4(ah[f2], Ab + sw128((uint32_t)(r * 128 + u * 16)));
                ldsm_x4(al[f2], Ab + sw128((uint32_t)(r * 128 + 64 + u * 16)));
            }
            #pragma unroll
            for (int ntp = 0; ntp < 4; ntp++) {
                int rb = n_base + ntp * 16 + ((lid >> 4) << 3) + (lid & 7);
                int u = ks * 2 + ((lid >> 3) & 1);
                uint32_t bh[4], bl[4];
                ldsm_x4(bh, Bb + sw128((uint32_t)(rb * 128 + u * 16)));
                ldsm_x4(bl, Bb + sw128((uint32_t)(rb * 128 + 64 + u * 16)));
                #pragma unroll
                for (int f2 = 0; f2 < 2; f2++) {
                    mma_bf16(acc[f2][ntp * 2], ah[f2], bh);
                    mma_bf16(acc[f2][ntp * 2], ah[f2], bl);
                    mma_bf16(acc[f2][ntp * 2], al[f2], bh);
                    mma_bf16(acc[f2][ntp * 2 + 1], ah[f2], bh + 2);
                    mma_bf16(acc[f2][ntp * 2 + 1], ah[f2], bl + 2);
                    mma_bf16(acc[f2][ntp * 2 + 1], al[f2], bh + 2);
                }
            }
        }
        __syncthreads();
    }

    // register-direct epilogue
    #pragma unroll
    for (int f2 = 0; f2 < 2; f2++) {
        #pragma unroll
        for (int rr = 0; rr < 2; rr++) {
            int r = row0 + m_base + f2 * 16 + grp + rr * 8;
            #pragma unroll
            for (int t = 0; t < 8; t++) {
                int col = col0 + n_base + t * 8 + qd * 2;
                float v0 = acc[f2][t][rr * 2 + 0] + bias[col];
                float v1 = acc[f2][t][rr * 2 + 1] + bias[col + 1];
                if (ACT == 1) {
                    v0 = 0.5f * v0 * (1.f + erff(v0 * 0.7071067811865476f));
                    v1 = 0.5f * v1 * (1.f + erff(v1 * 0.7071067811865476f));
                }
                if (RESID) {
                    float2 rv = *(const float2*)(resid + (size_t)r * C_ + col);
                    v0 += rv.x; v1 += rv.y;
                }
                if (OUTHL) {
                    *(uint32_t*)(outh + (size_t)r * ldo + col) = pack_hi(v0, v1);
                    *(uint32_t*)(outl + (size_t)r * ldo + col) = pack_lo(v0, v1);
                } else {
                    *(float2*)(outf + (size_t)r * ldo + col) = make_float2(v0, v1);
                }
            }
        }
    }
}

// ---------------- flash attention: Q/K/V bf16 hi/lo in, O bf16 hi/lo out ----------------
// SMEM: QH 16K | QL 16K | 2 KV stages (KH 8K | KL 8K | VH 8K | VL 8K) = 96KB
static constexpr int ATT_SMEM = 98304;

__global__ void __launch_bounds__(256)
attn2(const __nv_bfloat16* __restrict__ qh, const __nv_bfloat16* __restrict__ ql,
      __nv_bfloat16* __restrict__ oh, __nv_bfloat16* __restrict__ ol) {
    extern __shared__ char smem[];
    uint32_t sb = smem_to_u32(smem);
    const uint32_t QH = sb, QL = sb + 16384u;
    int tid = threadIdx.x, wid = tid >> 5, lid = tid & 31;
    int grp = lid >> 2, qd = lid & 3;
    int qt = blockIdx.x, n = blockIdx.y, b = blockIdx.z;
    size_t qrow0 = (size_t)(b * S_ + qt * 128);
    size_t obase = qrow0 * C_ + n * HD;
    int r0 = wid * 16;

    auto issue_kv = [&](int kt) {
        uint32_t st = sb + 32768u + (uint32_t)(kt & 1) * 32768u;
        #pragma unroll
        for (int it = 0; it < 8; it++) {
            int idx = tid + it * 256;
            int kv = idx >> 10, rem = idx & 1023;
            int hl = rem >> 9, rem2 = rem & 511, r = rem2 >> 3, u = rem2 & 7;
            const __nv_bfloat16* src = (hl ? ql : qh) +
                (size_t)(b * S_ + kt * 64 + r) * NQKV + 512 + kv * 512 + n * HD + u * 8;
            CP_ASYNC16(st + (uint32_t)(kv * 16384 + hl * 8192) +
                       sw128((uint32_t)(r * 128 + u * 16)), src);
        }
    };
    // prologue: Q + KV stage 0 in one group
    #pragma unroll
    for (int it = 0; it < 8; it++) {
        int idx = tid + it * 256;
        int hl = idx >> 10, rem = idx & 1023, r = rem >> 3, u = rem & 7;
        const __nv_bfloat16* src = (hl ? ql : qh) + (qrow0 + r) * NQKV + n * HD + u * 8;
        CP_ASYNC16((hl ? QL : QH) + sw128((uint32_t)(r * 128 + u * 16)), src);
    }
    issue_kv(0); CP_COMMIT();

    float Oa[8][4] = {};
    float m0 = -1e30f, m1 = -1e30f, l0 = 0.f, l1 = 0.f;

    for (int kt = 0; kt < 16; kt++) {
        if (kt < 15) { issue_kv(kt + 1); CP_COMMIT(); CP_WAIT1(); }
        else { CP_WAIT0(); }
        __syncthreads();
        uint32_t KHs = sb + 32768u + (uint32_t)(kt & 1) * 32768u;
        uint32_t KLs = KHs + 8192u, VHs = KHs + 16384u, VLs = KHs + 24576u;

        // S = Q K^T (scale pre-folded into Q weights)
        float Sc[8][4];
        #pragma unroll
        for (int nf = 0; nf < 8; nf++)
            Sc[nf][0] = Sc[nf][1] = Sc[nf][2] = Sc[nf][3] = 0.f;
        #pragma unroll
        for (int ks = 0; ks < 4; ks++) {
            uint32_t ah[4], al[4];
            {
                int r = r0 + (lid & 15);
                int u = ks * 2 + (lid >> 4);
                ldsm_x4(ah, QH + sw128((uint32_t)(r * 128 + u * 16)));
                ldsm_x4(al, QL + sw128((uint32_t)(r * 128 + u * 16)));
            }
            #pragma unroll
            for (int ntp = 0; ntp < 4; ntp++) {
                int rb = ntp * 16 + ((lid >> 4) << 3) + (lid & 7);
                int u = ks * 2 + ((lid >> 3) & 1);
                uint32_t bh[4], bl[4];
                ldsm_x4(bh, KHs + sw128((uint32_t)(rb * 128 + u * 16)));
                ldsm_x4(bl, KLs + sw128((uint32_t)(rb * 128 + u * 16)));
                mma_bf16(Sc[ntp * 2], ah, bh);
                mma_bf16(Sc[ntp * 2], ah, bl);
                mma_bf16(Sc[ntp * 2], al, bh);
                mma_bf16(Sc[ntp * 2 + 1], ah, bh + 2);
                mma_bf16(Sc[ntp * 2 + 1], ah, bl + 2);
                mma_bf16(Sc[ntp * 2 + 1], al, bh + 2);
            }
        }

        // warp-local online softmax (rows r0+grp, r0+grp+8)
        float mx0 = -1e30f, mx1 = -1e30f;
        #pragma unroll
        for (int nf = 0; nf < 8; nf++) {
            mx0 = fmaxf(mx0, fmaxf(Sc[nf][0], Sc[nf][1]));
            mx1 = fmaxf(mx1, fmaxf(Sc[nf][2], Sc[nf][3]));
        }
        mx0 = fmaxf(mx0, __shfl_xor_sync(0xffffffffu, mx0, 1));
        mx0 = fmaxf(mx0, __shfl_xor_sync(0xffffffffu, mx0, 2));
        mx1 = fmaxf(mx1, __shfl_xor_sync(0xffffffffu, mx1, 1));
        mx1 = fmaxf(mx1, __shfl_xor_sync(0xffffffffu, mx1, 2));
        float mn0 = fmaxf(m0, mx0), mn1 = fmaxf(m1, mx1);
        float al0 = __expf(m0 - mn0), al1 = __expf(m1 - mn1);
        float s0 = 0.f, s1 = 0.f;
        #pragma unroll
        for (int nf = 0; nf < 8; nf++) {
            Sc[nf][0] = __expf(Sc[nf][0] - mn0);
            Sc[nf][1] = __expf(Sc[nf][1] - mn0);
            Sc[nf][2] = __expf(Sc[nf][2] - mn1);
            Sc[nf][3] = __expf(Sc[nf][3] - mn1);
            s0 += Sc[nf][0] + Sc[nf][1];
            s1 += Sc[nf][2] + Sc[nf][3];
        }
        s0 += __shfl_xor_sync(0xffffffffu, s0, 1);
        s0 += __shfl_xor_sync(0xffffffffu, s0, 2);
        s1 += __shfl_xor_sync(0xffffffffu, s1, 1);
        s1 += __shfl_xor_sync(0xffffffffu, s1, 2);
        l0 = l0 * al0 + s0;
        l1 = l1 * al1 + s1;
        m0 = mn0; m1 = mn1;
        #pragma unroll
        for (int nf = 0; nf < 8; nf++) {
            Oa[nf][0] *= al0; Oa[nf][1] *= al0;
            Oa[nf][2] *= al1; Oa[nf][3] *= al1;
        }

        // O += P V  (P packed in registers; V fragments via ldmatrix.trans)
        #pragma unroll
        for (int t = 0; t < 4; t++) {
            uint32_t pah[4], pal[4];
            pah[0] = pack_hi(Sc[2 * t][0], Sc[2 * t][1]);
            pah[1] = pack_hi(Sc[2 * t][2], Sc[2 * t][3]);
            pah[2] = pack_hi(Sc[2 * t + 1][0], Sc[2 * t + 1][1]);
            pah[3] = pack_hi(Sc[2 * t + 1][2], Sc[2 * t + 1][3]);
            pal[0] = pack_lo(Sc[2 * t][0], Sc[2 * t][1]);
            pal[1] = pack_lo(Sc[2 * t][2], Sc[2 * t][3]);
            pal[2] = pack_lo(Sc[2 * t + 1][0], Sc[2 * t + 1][1]);
            pal[3] = pack_lo(Sc[2 * t + 1][2], Sc[2 * t + 1][3]);
            #pragma unroll
            for (int ndp = 0; ndp < 4; ndp++) {
                int rb = t * 16 + ((lid >> 3) & 1) * 8 + (lid & 7);
                int u = ndp * 2 + (lid >> 4);
                uint32_t bh[4], bl[4];
                ldsm_x4_t(bh, VHs + sw128((uint32_t)(rb * 128 + u * 16)));
                ldsm_x4_t(bl, VLs + sw128((uint32_t)(rb * 128 + u * 16)));
                mma_bf16(Oa[ndp * 2], pah, bh);
                mma_bf16(Oa[ndp * 2], pal, bh);
                mma_bf16(Oa[ndp * 2], pah, bl);
                mma_bf16(Oa[ndp * 2 + 1], pah, bh + 2);
                mma_bf16(Oa[ndp * 2 + 1], pal, bh + 2);
                mma_bf16(Oa[ndp * 2 + 1], pah, bl + 2);
            }
        }
        __syncthreads();
    }

    float li0 = 1.f / l0, li1 = 1.f / l1;
    int r = r0 + grp;
    #pragma unroll
    for (int nf = 0; nf < 8; nf++) {
        int col = nf * 8 + qd * 2;
        float a0 = Oa[nf][0] * li0, a1 = Oa[nf][1] * li0;
        float b0 = Oa[nf][2] * li1, b1 = Oa[nf][3] * li1;
        *(uint32_t*)(oh + obase + (size_t)r * C_ + col) = pack_hi(a0, a1);
        *(uint32_t*)(ol + obase + (size_t)r * C_ + col) = pack_lo(a0, a1);
        *(uint32_t*)(oh + obase + (size_t)(r + 8) * C_ + col) = pack_hi(b0, b1);
        *(uint32_t*)(ol + obase + (size_t)(r + 8) * C_ + col) = pack_lo(b0, b1);
    }
}

// ---------------- launch ----------------
extern "C" void kernel_launch(void* const* d_in, const int* in_sizes, int n_in,
                              void* d_out, int out_size) {
    (void)in_sizes; (void)n_in; (void)out_size;
    const float* x    = (const float*)d_in[0];
    const float* K_W  = (const float*)d_in[2];
    const float* K_b  = (const float*)d_in[3];
    const float* Q_W  = (const float*)d_in[4];
    const float* Q_b  = (const float*)d_in[5];
    const float* V_W  = (const float*)d_in[6];
    const float* V_b  = (const float*)d_in[7];
    const float* O_W  = (const float*)d_in[8];
    const float* O_b  = (const float*)d_in[9];
    const float* ln1g = (const float*)d_in[10];
    const float* ln1b = (const float*)d_in[11];
    const float* ln2g = (const float*)d_in[12];
    const float* ln2b = (const float*)d_in[13];
    const float* W1   = (const float*)d_in[14];
    const float* b1   = (const float*)d_in[15];
    const float* W2   = (const float*)d_in[16];
    const float* b2   = (const float*)d_in[17];
    float* out = (float*)d_out;

    float *p_xs, *p_out1, *p_fin, *p_bqkv;
    __nv_bfloat16 *p_resh, *p_resl, *p_qkvh, *p_qkvl, *p_oh, *p_ol, *p_hh, *p_hl,
                  *p_h1h, *p_h1l, *p_wqh, *p_wql, *p_woh, *p_wol,
                  *p_w1h, *p_w1l, *p_w2h, *p_w2l;
    cudaGetSymbolAddress((void**)&p_xs, g_xs);
    cudaGetSymbolAddress((void**)&p_out1, g_out1);
    cudaGetSymbolAddress((void**)&p_fin, g_fin);
    cudaGetSymbolAddress((void**)&p_bqkv, g_bqkv);
    cudaGetSymbolAddress((void**)&p_resh, g_res_h);
    cudaGetSymbolAddress((void**)&p_resl, g_res_l);
    cudaGetSymbolAddress((void**)&p_qkvh, g_qkv_h);
    cudaGetSymbolAddress((void**)&p_qkvl, g_qkv_l);
    cudaGetSymbolAddress((void**)&p_oh, g_o_h);
    cudaGetSymbolAddress((void**)&p_ol, g_o_l);
    cudaGetSymbolAddress((void**)&p_hh, g_h_h);
    cudaGetSymbolAddress((void**)&p_hl, g_h_l);
    cudaGetSymbolAddress((void**)&p_h1h, g_h1_h);
    cudaGetSymbolAddress((void**)&p_h1l, g_h1_l);
    cudaGetSymbolAddress((void**)&p_wqh, g_wqkv_h);
    cudaGetSymbolAddress((void**)&p_wql, g_wqkv_l);
    cudaGetSymbolAddress((void**)&p_woh, g_wo_h);
    cudaGetSymbolAddress((void**)&p_wol, g_wo_l);
    cudaGetSymbolAddress((void**)&p_w1h, g_w1_h);
    cudaGetSymbolAddress((void**)&p_w1l, g_w1_l);
    cudaGetSymbolAddress((void**)&p_w2h, g_w2_h);
    cudaGetSymbolAddress((void**)&p_w2l, g_w2_l);

    cudaFuncSetAttribute(attn2, cudaFuncAttributeMaxDynamicSharedMemorySize, ATT_SMEM);
    cudaFuncSetAttribute(tc_gemm2<0, 0, 1>, cudaFuncAttributeMaxDynamicSharedMemorySize, GEMM_SMEM);
    cudaFuncSetAttribute(tc_gemm2<0, 1, 0>, cudaFuncAttributeMaxDynamicSharedMemorySize, GEMM_SMEM);
    cudaFuncSetAttribute(tc_gemm2<1, 0, 1>, cudaFuncAttributeMaxDynamicSharedMemorySize, GEMM_SMEM);

    pack_qkvw<<<dim3(16, 2, 24), 256>>>(Q_W, K_W, V_W, p_wqh, p_wql);
    pack_w3<<<dim3(16, 16, 3), 256>>>(O_W, W1, W2, p_woh, p_wol, p_w1h, p_w1l, p_w2h, p_w2l);
    pack_bias<<<6, 256>>>(Q_b, K_b, V_b, p_bqkv);
    transpose_in<<<dim3(16, 256), 256>>>(x, p_xs);
    ln_rows_hl<<<M_, 256>>>(p_xs, ln1g, ln1b, p_resh, p_resl);
    tc_gemm2<0, 0, 1><<<dim3(12, 64), 256, GEMM_SMEM>>>(
        p_resh, p_resl, p_wqh, p_wql, p_bqkv, nullptr, nullptr, p_qkvh, p_qkvl, NQKV);
    attn2<<<dim3(8, 8, 8), 256, ATT_SMEM>>>(p_qkvh, p_qkvl, p_oh, p_ol);
    tc_gemm2<0, 1, 0><<<dim3(4, 64), 256, GEMM_SMEM>>>(
        p_oh, p_ol, p_woh, p_wol, O_b, p_xs, p_out1, nullptr, nullptr, C_);
    ln_rows_hl<<<M_, 256>>>(p_out1, ln2g, ln2b, p_hh, p_hl);
    tc_gemm2<1, 0, 1><<<dim3(4, 64), 256, GEMM_SMEM>>>(
        p_hh, p_hl, p_w1h, p_w1l, b1, nullptr, nullptr, p_h1h, p_h1l, C_);
    tc_gemm2<0, 1, 0><<<dim3(4, 64), 256, GEMM_SMEM>>>(
        p_h1h, p_h1l, p_w2h, p_w2l, b2, p_out1, p_fin, nullptr, nullptr, C_);
    transpose_out<<<dim3(16, 256), 256>>>(p_fin, out);
}